// round 1
// baseline (speedup 1.0000x reference)
#include <cuda_runtime.h>
#include <cstdint>
#include <cstddef>

#define SQ 2048
#define DMODEL 2048
#define NH 16
#define DHEAD 128

// ---------------- scratch (static device globals; no runtime allocation) ----
__device__ float g_Q[NH * SQ * DHEAD];
__device__ float g_K[NH * SQ * DHEAD];
__device__ float g_V[NH * SQ * DHEAD];
__device__ float g_scores[(size_t)NH * SQ * SQ];   // 256 MB
__device__ float g_attn[SQ * DMODEL];

// ---------------- tf32 helpers ---------------------------------------------
__device__ __forceinline__ float f2tf(float f) {
    uint32_t r;
    asm("cvt.rna.tf32.f32 %0, %1;" : "=r"(r) : "f"(f));
    return __uint_as_float(r);
}

// ---------------- block GEMM core: 128x128 tile, K-step 32 ------------------
// A: [M x K] row-major (pointer already offset to block-row base), lda given.
// TRANS_B == false: B is [N x K] row-major (offset to block-col base) -> C = A * B^T
// TRANS_B == true : B is [K x N] row-major, ldb = N-stride            -> C = A * B
// 256 threads = 8 warps, warp grid 4(m) x 2(n), warp tile 32x64.
// acc[mt][nt][i]: m16n8k8 accumulators.
template <bool TRANS_B>
__device__ __forceinline__ void gemm_tile(const float* __restrict__ A, int lda,
                                          const float* __restrict__ B, int ldb,
                                          int K, float acc[2][8][4]) {
    __shared__ float As[128][36];
    __shared__ float Bs[128][36];

    const int tid  = threadIdx.x;
    const int warp = tid >> 5, lane = tid & 31;
    const int wm   = warp >> 1, wn = warp & 1;
    const int g    = lane >> 2, c = lane & 3;

    for (int k0 = 0; k0 < K; k0 += 32) {
        // ---- load A tile (128 rows x 32 cols), cvt to tf32 ----
        {
            const int r  = tid >> 3;          // 0..31
            const int c4 = (tid & 7) << 2;    // 0..28
            #pragma unroll
            for (int s = 0; s < 4; s++) {
                const int row = r + s * 32;
                const float4 v = *reinterpret_cast<const float4*>(
                    &A[(size_t)row * lda + k0 + c4]);
                float4 w;
                w.x = f2tf(v.x); w.y = f2tf(v.y); w.z = f2tf(v.z); w.w = f2tf(v.w);
                *reinterpret_cast<float4*>(&As[row][c4]) = w;
            }
        }
        // ---- load B tile into Bs[n][k] ----
        if (!TRANS_B) {
            const int r  = tid >> 3;
            const int c4 = (tid & 7) << 2;
            #pragma unroll
            for (int s = 0; s < 4; s++) {
                const int row = r + s * 32;   // n
                const float4 v = *reinterpret_cast<const float4*>(
                    &B[(size_t)row * ldb + k0 + c4]);
                float4 w;
                w.x = f2tf(v.x); w.y = f2tf(v.y); w.z = f2tf(v.z); w.w = f2tf(v.w);
                *reinterpret_cast<float4*>(&Bs[row][c4]) = w;
            }
        } else {
            const int kr = tid >> 5;          // 0..7
            const int n4 = (tid & 31) << 2;   // 0..124
            #pragma unroll
            for (int s = 0; s < 4; s++) {
                const int kk = kr + s * 8;    // 0..31
                const float4 v = *reinterpret_cast<const float4*>(
                    &B[(size_t)(k0 + kk) * ldb + n4]);
                Bs[n4 + 0][kk] = f2tf(v.x);
                Bs[n4 + 1][kk] = f2tf(v.y);
                Bs[n4 + 2][kk] = f2tf(v.z);
                Bs[n4 + 3][kk] = f2tf(v.w);
            }
        }
        __syncthreads();

        // ---- compute ----
        #pragma unroll
        for (int kk = 0; kk < 32; kk += 8) {
            uint32_t af[2][4];
            #pragma unroll
            for (int mt = 0; mt < 2; mt++) {
                const int m0 = wm * 32 + mt * 16;
                af[mt][0] = __float_as_uint(As[m0 + g][kk + c]);
                af[mt][1] = __float_as_uint(As[m0 + g + 8][kk + c]);
                af[mt][2] = __float_as_uint(As[m0 + g][kk + c + 4]);
                af[mt][3] = __float_as_uint(As[m0 + g + 8][kk + c + 4]);
            }
            #pragma unroll
            for (int nt = 0; nt < 8; nt++) {
                const int n0 = wn * 64 + nt * 8;
                const uint32_t b0 = __float_as_uint(Bs[n0 + g][kk + c]);
                const uint32_t b1 = __float_as_uint(Bs[n0 + g][kk + c + 4]);
                #pragma unroll
                for (int mt = 0; mt < 2; mt++) {
                    asm volatile(
                        "mma.sync.aligned.m16n8k8.row.col.f32.tf32.tf32.f32 "
                        "{%0,%1,%2,%3}, {%4,%5,%6,%7}, {%8,%9}, {%0,%1,%2,%3};\n"
                        : "+f"(acc[mt][nt][0]), "+f"(acc[mt][nt][1]),
                          "+f"(acc[mt][nt][2]), "+f"(acc[mt][nt][3])
                        : "r"(af[mt][0]), "r"(af[mt][1]),
                          "r"(af[mt][2]), "r"(af[mt][3]),
                          "r"(b0), "r"(b1));
                }
            }
        }
        __syncthreads();
    }
}

// row/col of acc element i within the 128x128 block tile
__device__ __forceinline__ int acc_row(int wm, int mt, int g, int i) {
    return wm * 32 + mt * 16 + g + ((i >> 1) << 3);
}
__device__ __forceinline__ int acc_col(int wn, int nt, int c, int i) {
    return wn * 64 + nt * 8 + c * 2 + (i & 1);
}

// ---------------- kernel 1: QKV projections --------------------------------
__global__ __launch_bounds__(256) void qkv_kernel(const float* __restrict__ x,
                                                  const float* __restrict__ wq,
                                                  const float* __restrict__ wk,
                                                  const float* __restrict__ wv) {
    const int which = blockIdx.z;
    const float* W = (which == 0) ? wq : (which == 1) ? wk : wv;
    float* out = (which == 0) ? g_Q : (which == 1) ? g_K : g_V;

    const int rb = blockIdx.x * 128;   // s
    const int cb = blockIdx.y * 128;   // p
    float acc[2][8][4] = {};
    gemm_tile<false>(x + (size_t)rb * DMODEL, DMODEL,
                     W + (size_t)cb * DMODEL, DMODEL, DMODEL, acc);

    const int tid = threadIdx.x, warp = tid >> 5, lane = tid & 31;
    const int wm = warp >> 1, wn = warp & 1, g = lane >> 2, c = lane & 3;
    #pragma unroll
    for (int mt = 0; mt < 2; mt++)
        #pragma unroll
        for (int nt = 0; nt < 8; nt++)
            #pragma unroll
            for (int i = 0; i < 4; i++) {
                const int s = rb + acc_row(wm, mt, g, i);
                const int p = cb + acc_col(wn, nt, c, i);
                const int h = p >> 7, dh = p & 127;
                out[(size_t)h * SQ * DHEAD + (size_t)s * DHEAD + dh] = acc[mt][nt][i];
            }
}

// ---------------- kernel 2: RoPE in-place on Q and K ------------------------
__global__ void rope_kernel(const float* __restrict__ cosb,
                            const float* __restrict__ sinb) {
    const int t = blockIdx.x * blockDim.x + threadIdx.x;  // 2*16*2048*64
    const int d  = t & 63;
    const int s  = (t >> 6) & (SQ - 1);
    const int h  = (t >> 17) & (NH - 1);
    const int qk = t >> 21;
    float* p = (qk ? g_K : g_Q) + (size_t)h * SQ * DHEAD + (size_t)s * DHEAD;
    const float x0 = p[d], x1 = p[d + 64];
    const float c0 = cosb[s * DHEAD + d],      s0 = sinb[s * DHEAD + d];
    const float c1 = cosb[s * DHEAD + d + 64], s1 = sinb[s * DHEAD + d + 64];
    p[d]      = x0 * c0 - x1 * s0;   // rotate_half: first half uses -x2
    p[d + 64] = x1 * c1 + x0 * s1;   // second half uses +x1
}

// ---------------- kernel 3: scores = tanh(QK^T/sqrt(dh)/50)*50, masked ------
__global__ __launch_bounds__(256) void scores_kernel() {
    const int qt = blockIdx.x, kt = blockIdx.y, h = blockIdx.z;
    if (kt > qt) return;  // strictly-upper tiles never computed nor read
    const int rb = qt * 128, cb = kt * 128;
    float acc[2][8][4] = {};
    gemm_tile<false>(g_Q + (size_t)h * SQ * DHEAD + (size_t)rb * DHEAD, DHEAD,
                     g_K + (size_t)h * SQ * DHEAD + (size_t)cb * DHEAD, DHEAD,
                     DHEAD, acc);

    const int tid = threadIdx.x, warp = tid >> 5, lane = tid & 31;
    const int wm = warp >> 1, wn = warp & 1, g = lane >> 2, c = lane & 3;
    float* out = g_scores + (size_t)h * SQ * SQ;
    #pragma unroll
    for (int mt = 0; mt < 2; mt++)
        #pragma unroll
        for (int nt = 0; nt < 8; nt++)
            #pragma unroll
            for (int i = 0; i < 4; i++) {
                const int q = rb + acc_row(wm, mt, g, i);
                const int k = cb + acc_col(wn, nt, c, i);
                float v = acc[mt][nt][i] * 0.08838834764831845f;  // 1/sqrt(128)
                v = tanhf(v * 0.02f) * 50.0f;
                if (k > q) v = -1e30f;  // causal; exp -> exact 0 like ref's -1e9
                out[(size_t)q * SQ + k] = v;
            }
}

// ---------------- kernel 4: row softmax in-place ----------------------------
__global__ void softmax_kernel() {
    const int b = blockIdx.x;
    const int h = b >> 11, q = b & (SQ - 1);
    float* row = g_scores + (size_t)h * SQ * SQ + (size_t)q * SQ;
    const int kl = ((q >> 7) + 1) << 7;   // round (q+1) up to tile boundary
    const int tid = threadIdx.x;
    __shared__ float red[256];

    float m = -1e30f;
    for (int k = tid; k < kl; k += 256) m = fmaxf(m, row[k]);
    red[tid] = m; __syncthreads();
    for (int s = 128; s > 0; s >>= 1) {
        if (tid < s) red[tid] = fmaxf(red[tid], red[tid + s]);
        __syncthreads();
    }
    m = red[0]; __syncthreads();

    float sum = 0.f;
    for (int k = tid; k < kl; k += 256) {
        const float e = expf(row[k] - m);
        row[k] = e; sum += e;
    }
    red[tid] = sum; __syncthreads();
    for (int s = 128; s > 0; s >>= 1) {
        if (tid < s) red[tid] += red[tid + s];
        __syncthreads();
    }
    const float inv = 1.0f / red[0];
    for (int k = tid; k < kl; k += 256) row[k] *= inv;
}

// ---------------- kernel 5: out = P @ V (causal K range) --------------------
__global__ __launch_bounds__(256) void pv_kernel() {
    const int qt = blockIdx.x, h = blockIdx.z;
    const int rb = qt * 128;
    const int K = (qt + 1) * 128;   // zeros beyond q within tile handled by softmax
    float acc[2][8][4] = {};
    gemm_tile<true>(g_scores + (size_t)h * SQ * SQ + (size_t)rb * SQ, SQ,
                    g_V + (size_t)h * SQ * DHEAD, DHEAD, K, acc);

    const int tid = threadIdx.x, warp = tid >> 5, lane = tid & 31;
    const int wm = warp >> 1, wn = warp & 1, g = lane >> 2, c = lane & 3;
    #pragma unroll
    for (int mt = 0; mt < 2; mt++)
        #pragma unroll
        for (int nt = 0; nt < 8; nt++)
            #pragma unroll
            for (int i = 0; i < 4; i++) {
                const int q  = rb + acc_row(wm, mt, g, i);
                const int dh = acc_col(wn, nt, c, i);   // N = 128 = full head
                g_attn[(size_t)q * DMODEL + h * DHEAD + dh] = acc[mt][nt][i];
            }
}

// ---------------- kernel 6: output projection -------------------------------
__global__ __launch_bounds__(256) void oproj_kernel(const float* __restrict__ wo,
                                                    float* __restrict__ out) {
    const int rb = blockIdx.x * 128, cb = blockIdx.y * 128;
    float acc[2][8][4] = {};
    gemm_tile<false>(g_attn + (size_t)rb * DMODEL, DMODEL,
                     wo + (size_t)cb * DMODEL, DMODEL, DMODEL, acc);

    const int tid = threadIdx.x, warp = tid >> 5, lane = tid & 31;
    const int wm = warp >> 1, wn = warp & 1, g = lane >> 2, c = lane & 3;
    #pragma unroll
    for (int mt = 0; mt < 2; mt++)
        #pragma unroll
        for (int nt = 0; nt < 8; nt++)
            #pragma unroll
            for (int i = 0; i < 4; i++) {
                const int s = rb + acc_row(wm, mt, g, i);
                const int d = cb + acc_col(wn, nt, c, i);
                out[(size_t)s * DMODEL + d] = acc[mt][nt][i];
            }
}

// ---------------- launch ----------------------------------------------------
extern "C" void kernel_launch(void* const* d_in, const int* in_sizes, int n_in,
                              void* d_out, int out_size) {
    (void)in_sizes; (void)n_in; (void)out_size;
    const float* x  = (const float*)d_in[0];
    const float* rc = (const float*)d_in[1];
    const float* rs = (const float*)d_in[2];
    // d_in[3] = additive mask; causal masking implemented directly.
    const float* wq = (const float*)d_in[4];
    const float* wk = (const float*)d_in[5];
    const float* wv = (const float*)d_in[6];
    const float* wo = (const float*)d_in[7];
    float* out = (float*)d_out;

    qkv_kernel<<<dim3(16, 16, 3), 256>>>(x, wq, wk, wv);
    rope_kernel<<<16384, 256>>>(rc, rs);
    scores_kernel<<<dim3(16, 16, 16), 256>>>();
    softmax_kernel<<<NH * SQ, 256>>>();
    pv_kernel<<<dim3(16, 1, 16), 256>>>();
    oproj_kernel<<<dim3(16, 16), 256>>>(wo, out);
}

// round 2
// speedup vs baseline: 1.2106x; 1.2106x over previous
#include <cuda_runtime.h>
#include <cstdint>
#include <cstddef>

#define SQ 2048
#define DMODEL 2048
#define NH 16
#define DHEAD 128
#define PS_LD 132
#define BS_LD 36

// ---------------- scratch (static device globals; no runtime allocation) ----
__device__ float g_Q[NH * SQ * DHEAD];
__device__ float g_K[NH * SQ * DHEAD];
__device__ float g_V[NH * SQ * DHEAD];
__device__ float g_attn[SQ * DMODEL];

// ---------------- tf32 helpers ---------------------------------------------
__device__ __forceinline__ float f2tf(float f) {
    uint32_t r;
    asm("cvt.rna.tf32.f32 %0, %1;" : "=r"(r) : "f"(f));
    return __uint_as_float(r);
}

__device__ __forceinline__ void mma_tf32(float acc[4], const uint32_t a[4],
                                         uint32_t b0, uint32_t b1) {
    asm volatile(
        "mma.sync.aligned.m16n8k8.row.col.f32.tf32.tf32.f32 "
        "{%0,%1,%2,%3}, {%4,%5,%6,%7}, {%8,%9}, {%0,%1,%2,%3};\n"
        : "+f"(acc[0]), "+f"(acc[1]), "+f"(acc[2]), "+f"(acc[3])
        : "r"(a[0]), "r"(a[1]), "r"(a[2]), "r"(a[3]), "r"(b0), "r"(b1));
}

// ---------------- block GEMM core: 128x128 tile, K-step 32 ------------------
template <bool TRANS_B>
__device__ __forceinline__ void gemm_tile(const float* __restrict__ A, int lda,
                                          const float* __restrict__ B, int ldb,
                                          int K, float acc[2][8][4]) {
    __shared__ float As[128][36];
    __shared__ float Bs[128][36];

    const int tid  = threadIdx.x;
    const int warp = tid >> 5, lane = tid & 31;
    const int wm   = warp >> 1, wn = warp & 1;
    const int g    = lane >> 2, c = lane & 3;

    for (int k0 = 0; k0 < K; k0 += 32) {
        {
            const int r  = tid >> 3;
            const int c4 = (tid & 7) << 2;
            #pragma unroll
            for (int s = 0; s < 4; s++) {
                const int row = r + s * 32;
                const float4 v = *reinterpret_cast<const float4*>(
                    &A[(size_t)row * lda + k0 + c4]);
                float4 w;
                w.x = f2tf(v.x); w.y = f2tf(v.y); w.z = f2tf(v.z); w.w = f2tf(v.w);
                *reinterpret_cast<float4*>(&As[row][c4]) = w;
            }
        }
        if (!TRANS_B) {
            const int r  = tid >> 3;
            const int c4 = (tid & 7) << 2;
            #pragma unroll
            for (int s = 0; s < 4; s++) {
                const int row = r + s * 32;
                const float4 v = *reinterpret_cast<const float4*>(
                    &B[(size_t)row * ldb + k0 + c4]);
                float4 w;
                w.x = f2tf(v.x); w.y = f2tf(v.y); w.z = f2tf(v.z); w.w = f2tf(v.w);
                *reinterpret_cast<float4*>(&Bs[row][c4]) = w;
            }
        } else {
            const int kr = tid >> 5;
            const int n4 = (tid & 31) << 2;
            #pragma unroll
            for (int s = 0; s < 4; s++) {
                const int kk = kr + s * 8;
                const float4 v = *reinterpret_cast<const float4*>(
                    &B[(size_t)(k0 + kk) * ldb + n4]);
                Bs[n4 + 0][kk] = f2tf(v.x);
                Bs[n4 + 1][kk] = f2tf(v.y);
                Bs[n4 + 2][kk] = f2tf(v.z);
                Bs[n4 + 3][kk] = f2tf(v.w);
            }
        }
        __syncthreads();

        #pragma unroll
        for (int kk = 0; kk < 32; kk += 8) {
            uint32_t af[2][4];
            #pragma unroll
            for (int mt = 0; mt < 2; mt++) {
                const int m0 = wm * 32 + mt * 16;
                af[mt][0] = __float_as_uint(As[m0 + g][kk + c]);
                af[mt][1] = __float_as_uint(As[m0 + g + 8][kk + c]);
                af[mt][2] = __float_as_uint(As[m0 + g][kk + c + 4]);
                af[mt][3] = __float_as_uint(As[m0 + g + 8][kk + c + 4]);
            }
            #pragma unroll
            for (int nt = 0; nt < 8; nt++) {
                const int n0 = wn * 64 + nt * 8;
                const uint32_t b0 = __float_as_uint(Bs[n0 + g][kk + c]);
                const uint32_t b1 = __float_as_uint(Bs[n0 + g][kk + c + 4]);
                #pragma unroll
                for (int mt = 0; mt < 2; mt++)
                    mma_tf32(acc[mt][nt], af[mt], b0, b1);
            }
        }
        __syncthreads();
    }
}

__device__ __forceinline__ int acc_row(int wm, int mt, int g, int i) {
    return wm * 32 + mt * 16 + g + ((i >> 1) << 3);
}
__device__ __forceinline__ int acc_col(int wn, int nt, int c, int i) {
    return wn * 64 + nt * 8 + c * 2 + (i & 1);
}

// ---------------- kernel 1: QKV projections --------------------------------
__global__ __launch_bounds__(256) void qkv_kernel(const float* __restrict__ x,
                                                  const float* __restrict__ wq,
                                                  const float* __restrict__ wk,
                                                  const float* __restrict__ wv) {
    const int which = blockIdx.z;
    const float* W = (which == 0) ? wq : (which == 1) ? wk : wv;
    float* out = (which == 0) ? g_Q : (which == 1) ? g_K : g_V;

    const int rb = blockIdx.x * 128;
    const int cb = blockIdx.y * 128;
    float acc[2][8][4] = {};
    gemm_tile<false>(x + (size_t)rb * DMODEL, DMODEL,
                     W + (size_t)cb * DMODEL, DMODEL, DMODEL, acc);

    const int tid = threadIdx.x, warp = tid >> 5, lane = tid & 31;
    const int wm = warp >> 1, wn = warp & 1, g = lane >> 2, c = lane & 3;
    #pragma unroll
    for (int mt = 0; mt < 2; mt++)
        #pragma unroll
        for (int nt = 0; nt < 8; nt++)
            #pragma unroll
            for (int i = 0; i < 4; i++) {
                const int s = rb + acc_row(wm, mt, g, i);
                const int p = cb + acc_col(wn, nt, c, i);
                const int h = p >> 7, dh = p & 127;
                out[(size_t)h * SQ * DHEAD + (size_t)s * DHEAD + dh] = acc[mt][nt][i];
            }
}

// ---------------- kernel 2: RoPE in-place on Q and K ------------------------
__global__ void rope_kernel(const float* __restrict__ cosb,
                            const float* __restrict__ sinb) {
    const int t = blockIdx.x * blockDim.x + threadIdx.x;
    const int d  = t & 63;
    const int s  = (t >> 6) & (SQ - 1);
    const int h  = (t >> 17) & (NH - 1);
    const int qk = t >> 21;
    float* p = (qk ? g_K : g_Q) + (size_t)h * SQ * DHEAD + (size_t)s * DHEAD;
    const float x0 = p[d], x1 = p[d + 64];
    const float c0 = cosb[s * DHEAD + d],      s0 = sinb[s * DHEAD + d];
    const float c1 = cosb[s * DHEAD + d + 64], s1 = sinb[s * DHEAD + d + 64];
    p[d]      = x0 * c0 - x1 * s0;
    p[d + 64] = x1 * c1 + x0 * s1;
}

// ---------------- kernel 3: flash attention (fused S/softmax/PV) ------------
// grid: 256 blocks 1-D; bid -> qt = 15 - bid/16 (long tiles first), h = bid%16
__global__ __launch_bounds__(256) void flash_kernel() {
    extern __shared__ float sm[];
    float* Qs      = sm;                       // 128 * PS_LD
    float* Ps      = Qs + 128 * PS_LD;         // 128 * PS_LD
    float* Bs      = Ps + 128 * PS_LD;         // 128 * BS_LD
    float* m_state = Bs + 128 * BS_LD;         // 128
    float* l_state = m_state + 128;            // 128
    float* rmax    = l_state + 128;            // 2 * 128
    float* rsum    = rmax + 256;               // 2 * 128

    const int bid = blockIdx.x;
    const int qt  = 15 - (bid >> 4);
    const int h   = bid & 15;
    const int rb  = qt * 128;

    const int tid = threadIdx.x, warp = tid >> 5, lane = tid & 31;
    const int wm = warp >> 1, wn = warp & 1, g = lane >> 2, c = lane & 3;
    const int m0b = wm * 32;

    if (tid < 128) { m_state[tid] = -1e30f; l_state[tid] = 0.f; }

    // load Q tile -> Qs (tf32)
    {
        const float* Qg = g_Q + (size_t)h * SQ * DHEAD + (size_t)rb * DHEAD;
        const int r = tid >> 3, c4 = (tid & 7) << 2;
        #pragma unroll
        for (int s = 0; s < 4; s++)
            #pragma unroll
            for (int cc = 0; cc < 4; cc++) {
                const int row = r + s * 32, col = c4 + cc * 32;
                const float4 v = *reinterpret_cast<const float4*>(
                    &Qg[(size_t)row * DHEAD + col]);
                float4 w;
                w.x = f2tf(v.x); w.y = f2tf(v.y); w.z = f2tf(v.z); w.w = f2tf(v.w);
                *reinterpret_cast<float4*>(&Qs[row * PS_LD + col]) = w;
            }
    }
    __syncthreads();

    float acc_o[2][8][4] = {};

    for (int kt = 0; kt <= qt; kt++) {
        const int cb = kt * 128;
        const float* Kg = g_K + (size_t)h * SQ * DHEAD + (size_t)cb * DHEAD;
        float acc[2][8][4] = {};

        // ---- S = Q @ K^T ----
        for (int k0 = 0; k0 < DHEAD; k0 += 32) {
            const int r = tid >> 3, c4 = (tid & 7) << 2;
            #pragma unroll
            for (int s = 0; s < 4; s++) {
                const int row = r + s * 32;
                const float4 v = *reinterpret_cast<const float4*>(
                    &Kg[(size_t)row * DHEAD + k0 + c4]);
                float4 w;
                w.x = f2tf(v.x); w.y = f2tf(v.y); w.z = f2tf(v.z); w.w = f2tf(v.w);
                *reinterpret_cast<float4*>(&Bs[row * BS_LD + c4]) = w;
            }
            __syncthreads();
            #pragma unroll
            for (int kk = 0; kk < 32; kk += 8) {
                uint32_t af[2][4];
                #pragma unroll
                for (int mt = 0; mt < 2; mt++) {
                    const float* q0 = &Qs[(m0b + mt * 16 + g) * PS_LD + k0 + kk + c];
                    af[mt][0] = __float_as_uint(q0[0]);
                    af[mt][1] = __float_as_uint(q0[8 * PS_LD]);
                    af[mt][2] = __float_as_uint(q0[4]);
                    af[mt][3] = __float_as_uint(q0[8 * PS_LD + 4]);
                }
                #pragma unroll
                for (int nt = 0; nt < 8; nt++) {
                    const int n0 = wn * 64 + nt * 8;
                    const uint32_t b0 = __float_as_uint(Bs[(n0 + g) * BS_LD + kk + c]);
                    const uint32_t b1 = __float_as_uint(Bs[(n0 + g) * BS_LD + kk + c + 4]);
                    #pragma unroll
                    for (int mt = 0; mt < 2; mt++)
                        mma_tf32(acc[mt][nt], af[mt], b0, b1);
                }
            }
            __syncthreads();
        }

        // ---- softcap + mask + per-thread row max ----
        float pmax[2][2] = {{-1e30f, -1e30f}, {-1e30f, -1e30f}};
        #pragma unroll
        for (int mt = 0; mt < 2; mt++)
            #pragma unroll
            for (int nt = 0; nt < 8; nt++)
                #pragma unroll
                for (int i = 0; i < 4; i++) {
                    float v = acc[mt][nt][i] * 0.08838834764831845f;
                    v = tanhf(v * 0.02f) * 50.0f;
                    if (kt == qt) {
                        const int rr = acc_row(wm, mt, g, i);
                        const int cl = acc_col(wn, nt, c, i);
                        if (cl > rr) v = -1e30f;
                    }
                    acc[mt][nt][i] = v;
                    pmax[mt][i >> 1] = fmaxf(pmax[mt][i >> 1], v);
                }
        #pragma unroll
        for (int mt = 0; mt < 2; mt++)
            #pragma unroll
            for (int rh = 0; rh < 2; rh++) {
                float p = pmax[mt][rh];
                p = fmaxf(p, __shfl_xor_sync(0xffffffffu, p, 1));
                p = fmaxf(p, __shfl_xor_sync(0xffffffffu, p, 2));
                pmax[mt][rh] = p;
            }
        if (c == 0) {
            #pragma unroll
            for (int mt = 0; mt < 2; mt++)
                #pragma unroll
                for (int rh = 0; rh < 2; rh++)
                    rmax[wn * 128 + m0b + mt * 16 + rh * 8 + g] = pmax[mt][rh];
        }
        __syncthreads();

        // ---- m_new, scale, P = exp(v - m_new), row sums ----
        float mnew[2][2], scal[2][2], psum[2][2] = {};
        #pragma unroll
        for (int mt = 0; mt < 2; mt++)
            #pragma unroll
            for (int rh = 0; rh < 2; rh++) {
                const int r = m0b + mt * 16 + rh * 8 + g;
                const float mo = m_state[r];
                const float tm = fmaxf(rmax[r], rmax[128 + r]);
                const float mn = fmaxf(mo, tm);
                mnew[mt][rh] = mn;
                scal[mt][rh] = __expf(mo - mn);
            }
        #pragma unroll
        for (int mt = 0; mt < 2; mt++)
            #pragma unroll
            for (int nt = 0; nt < 8; nt++)
                #pragma unroll
                for (int i = 0; i < 4; i++) {
                    const int rr = acc_row(wm, mt, g, i);
                    const int cl = acc_col(wn, nt, c, i);
                    const float p = expf(acc[mt][nt][i] - mnew[mt][i >> 1]);
                    psum[mt][i >> 1] += p;
                    Ps[rr * PS_LD + cl] = f2tf(p);
                }
        #pragma unroll
        for (int mt = 0; mt < 2; mt++)
            #pragma unroll
            for (int rh = 0; rh < 2; rh++) {
                float p = psum[mt][rh];
                p += __shfl_xor_sync(0xffffffffu, p, 1);
                p += __shfl_xor_sync(0xffffffffu, p, 2);
                psum[mt][rh] = p;
            }
        if (c == 0) {
            #pragma unroll
            for (int mt = 0; mt < 2; mt++)
                #pragma unroll
                for (int rh = 0; rh < 2; rh++)
                    rsum[wn * 128 + m0b + mt * 16 + rh * 8 + g] = psum[mt][rh];
        }
        __syncthreads();

        if (wn == 0 && c == 0) {
            #pragma unroll
            for (int mt = 0; mt < 2; mt++)
                #pragma unroll
                for (int rh = 0; rh < 2; rh++) {
                    const int r = m0b + mt * 16 + rh * 8 + g;
                    l_state[r] = l_state[r] * scal[mt][rh] + rsum[r] + rsum[128 + r];
                    m_state[r] = mnew[mt][rh];
                }
        }
        #pragma unroll
        for (int mt = 0; mt < 2; mt++)
            #pragma unroll
            for (int nt = 0; nt < 8; nt++)
                #pragma unroll
                for (int i = 0; i < 4; i++)
                    acc_o[mt][nt][i] *= scal[mt][i >> 1];

        // ---- O += P @ V ----
        const float* Vg = g_V + (size_t)h * SQ * DHEAD + (size_t)cb * DHEAD;
        for (int k0 = 0; k0 < 128; k0 += 32) {
            const int kr = tid >> 5, n4 = (tid & 31) << 2;
            #pragma unroll
            for (int s = 0; s < 4; s++) {
                const int kk = kr + s * 8;
                const float4 v = *reinterpret_cast<const float4*>(
                    &Vg[(size_t)(k0 + kk) * DHEAD + n4]);
                Bs[(n4 + 0) * BS_LD + kk] = f2tf(v.x);
                Bs[(n4 + 1) * BS_LD + kk] = f2tf(v.y);
                Bs[(n4 + 2) * BS_LD + kk] = f2tf(v.z);
                Bs[(n4 + 3) * BS_LD + kk] = f2tf(v.w);
            }
            __syncthreads();
            #pragma unroll
            for (int kk = 0; kk < 32; kk += 8) {
                uint32_t af[2][4];
                #pragma unroll
                for (int mt = 0; mt < 2; mt++) {
                    const float* p0 = &Ps[(m0b + mt * 16 + g) * PS_LD + k0 + kk + c];
                    af[mt][0] = __float_as_uint(p0[0]);
                    af[mt][1] = __float_as_uint(p0[8 * PS_LD]);
                    af[mt][2] = __float_as_uint(p0[4]);
                    af[mt][3] = __float_as_uint(p0[8 * PS_LD + 4]);
                }
                #pragma unroll
                for (int nt = 0; nt < 8; nt++) {
                    const int n0 = wn * 64 + nt * 8;
                    const uint32_t b0 = __float_as_uint(Bs[(n0 + g) * BS_LD + kk + c]);
                    const uint32_t b1 = __float_as_uint(Bs[(n0 + g) * BS_LD + kk + c + 4]);
                    #pragma unroll
                    for (int mt = 0; mt < 2; mt++)
                        mma_tf32(acc_o[mt][nt], af[mt], b0, b1);
                }
            }
            __syncthreads();
        }
    }

    // ---- normalize + store ----
    float inv[2][2];
    #pragma unroll
    for (int mt = 0; mt < 2; mt++)
        #pragma unroll
        for (int rh = 0; rh < 2; rh++)
            inv[mt][rh] = 1.0f / l_state[m0b + mt * 16 + rh * 8 + g];
    #pragma unroll
    for (int mt = 0; mt < 2; mt++)
        #pragma unroll
        for (int nt = 0; nt < 8; nt++)
            #pragma unroll
            for (int i = 0; i < 4; i++) {
                const int q  = rb + acc_row(wm, mt, g, i);
                const int dh = acc_col(wn, nt, c, i);
                g_attn[(size_t)q * DMODEL + h * DHEAD + dh] =
                    acc_o[mt][nt][i] * inv[mt][i >> 1];
            }
}

// ---------------- kernel 4: output projection -------------------------------
__global__ __launch_bounds__(256) void oproj_kernel(const float* __restrict__ wo,
                                                    float* __restrict__ out) {
    const int rb = blockIdx.x * 128, cb = blockIdx.y * 128;
    float acc[2][8][4] = {};
    gemm_tile<false>(g_attn + (size_t)rb * DMODEL, DMODEL,
                     wo + (size_t)cb * DMODEL, DMODEL, DMODEL, acc);

    const int tid = threadIdx.x, warp = tid >> 5, lane = tid & 31;
    const int wm = warp >> 1, wn = warp & 1, g = lane >> 2, c = lane & 3;
    #pragma unroll
    for (int mt = 0; mt < 2; mt++)
        #pragma unroll
        for (int nt = 0; nt < 8; nt++)
            #pragma unroll
            for (int i = 0; i < 4; i++) {
                const int s = rb + acc_row(wm, mt, g, i);
                const int d = cb + acc_col(wn, nt, c, i);
                out[(size_t)s * DMODEL + d] = acc[mt][nt][i];
            }
}

// ---------------- launch ----------------------------------------------------
extern "C" void kernel_launch(void* const* d_in, const int* in_sizes, int n_in,
                              void* d_out, int out_size) {
    (void)in_sizes; (void)n_in; (void)out_size;
    const float* x  = (const float*)d_in[0];
    const float* rc = (const float*)d_in[1];
    const float* rs = (const float*)d_in[2];
    const float* wq = (const float*)d_in[4];
    const float* wk = (const float*)d_in[5];
    const float* wv = (const float*)d_in[6];
    const float* wo = (const float*)d_in[7];
    float* out = (float*)d_out;

    const int flash_smem = (2 * 128 * PS_LD + 128 * BS_LD + 6 * 128) * (int)sizeof(float);
    cudaFuncSetAttribute(flash_kernel,
                         cudaFuncAttributeMaxDynamicSharedMemorySize, flash_smem);

    qkv_kernel<<<dim3(16, 16, 3), 256>>>(x, wq, wk, wv);
    rope_kernel<<<16384, 256>>>(rc, rs);
    flash_kernel<<<256, 256, flash_smem>>>();
    oproj_kernel<<<dim3(16, 16), 256>>>(wo, out);
}

// round 4
// speedup vs baseline: 1.2974x; 1.0717x over previous
#include <cuda_runtime.h>
#include <cstdint>
#include <cstddef>

#define SQ 2048
#define DMODEL 2048
#define NH 16
#define DHEAD 128
#define PS_LD 132
#define BS_LD 36
#define NCH (DMODEL / 32)     // 64 K-chunks for dense GEMMs

// dense double-buffer smem: 2 stages x (A + B) x 128x36 floats
#define TILE_F (128 * 36)
#define DENSE_SMEM_F (4 * TILE_F)

// ---------------- scratch (static device globals; no runtime allocation) ----
__device__ float g_Q[NH * SQ * DHEAD];
__device__ float g_K[NH * SQ * DHEAD];
__device__ float g_V[NH * SQ * DHEAD];
__device__ float g_attn[SQ * DMODEL];

// ---------------- helpers ---------------------------------------------------
__device__ __forceinline__ float f2tf(float f) {
    uint32_t r;
    asm("cvt.rna.tf32.f32 %0, %1;" : "=r"(r) : "f"(f));
    return __uint_as_float(r);
}

__device__ __forceinline__ float fast_tanh(float x) {
    // tanh(x) = 1 - 2/(e^(2x)+1); __expf-based, rel err ~1e-6
    const float e = __expf(2.0f * x);
    return 1.0f - 2.0f / (e + 1.0f);
}

__device__ __forceinline__ void mma_tf32(float acc[4], const uint32_t a[4],
                                         uint32_t b0, uint32_t b1) {
    asm volatile(
        "mma.sync.aligned.m16n8k8.row.col.f32.tf32.tf32.f32 "
        "{%0,%1,%2,%3}, {%4,%5,%6,%7}, {%8,%9}, {%0,%1,%2,%3};\n"
        : "+f"(acc[0]), "+f"(acc[1]), "+f"(acc[2]), "+f"(acc[3])
        : "r"(a[0]), "r"(a[1]), "r"(a[2]), "r"(a[3]), "r"(b0), "r"(b1));
}

__device__ __forceinline__ int acc_row(int wm, int mt, int g, int i) {
    return wm * 32 + mt * 16 + g + ((i >> 1) << 3);
}
__device__ __forceinline__ int acc_col(int wn, int nt, int c, int i) {
    return wn * 64 + nt * 8 + c * 2 + (i & 1);
}

// ---------------- dense GEMM core: 128x128 tile, double-buffered ------------
// C = A * B^T ; A [128 x 2048] rows offset, B [128 x 2048] rows offset.
__device__ __forceinline__ void gemm128_db(const float* __restrict__ A, int lda,
                                           const float* __restrict__ B, int ldb,
                                           float acc[2][8][4], float* sm) {
    float* As[2] = { sm,              sm + TILE_F };
    float* Bs[2] = { sm + 2 * TILE_F, sm + 3 * TILE_F };

    const int tid  = threadIdx.x;
    const int warp = tid >> 5, lane = tid & 31;
    const int wm   = warp >> 1, wn = warp & 1;
    const int g    = lane >> 2, c = lane & 3;
    const int r    = tid >> 3;           // 0..31
    const int c4   = (tid & 7) << 2;     // 0..28

    float4 ra[4], rb[4];

    // prologue: chunk 0 -> regs -> stage 0
    #pragma unroll
    for (int s = 0; s < 4; s++) {
        ra[s] = *reinterpret_cast<const float4*>(&A[(size_t)(r + s * 32) * lda + c4]);
        rb[s] = *reinterpret_cast<const float4*>(&B[(size_t)(r + s * 32) * ldb + c4]);
    }
    #pragma unroll
    for (int s = 0; s < 4; s++) {
        float4 wA, wB;
        wA.x = f2tf(ra[s].x); wA.y = f2tf(ra[s].y); wA.z = f2tf(ra[s].z); wA.w = f2tf(ra[s].w);
        wB.x = f2tf(rb[s].x); wB.y = f2tf(rb[s].y); wB.z = f2tf(rb[s].z); wB.w = f2tf(rb[s].w);
        *reinterpret_cast<float4*>(&As[0][(r + s * 32) * 36 + c4]) = wA;
        *reinterpret_cast<float4*>(&Bs[0][(r + s * 32) * 36 + c4]) = wB;
    }

    for (int ch = 0; ch < NCH; ch++) {
        const int buf = ch & 1;
        __syncthreads();   // stage `buf` filled & visible; prev compute done

        if (ch + 1 < NCH) {
            const int k0 = (ch + 1) * 32;
            #pragma unroll
            for (int s = 0; s < 4; s++) {
                ra[s] = *reinterpret_cast<const float4*>(
                    &A[(size_t)(r + s * 32) * lda + k0 + c4]);
                rb[s] = *reinterpret_cast<const float4*>(
                    &B[(size_t)(r + s * 32) * ldb + k0 + c4]);
            }
        }

        const float* Ab = As[buf];
        const float* Bb = Bs[buf];
        #pragma unroll
        for (int kk = 0; kk < 32; kk += 8) {
            uint32_t af[2][4];
            #pragma unroll
            for (int mt = 0; mt < 2; mt++) {
                const float* a0 = &Ab[(wm * 32 + mt * 16 + g) * 36 + kk + c];
                af[mt][0] = __float_as_uint(a0[0]);
                af[mt][1] = __float_as_uint(a0[8 * 36]);
                af[mt][2] = __float_as_uint(a0[4]);
                af[mt][3] = __float_as_uint(a0[8 * 36 + 4]);
            }
            #pragma unroll
            for (int nt = 0; nt < 8; nt++) {
                const int n0 = wn * 64 + nt * 8;
                const uint32_t b0 = __float_as_uint(Bb[(n0 + g) * 36 + kk + c]);
                const uint32_t b1 = __float_as_uint(Bb[(n0 + g) * 36 + kk + c + 4]);
                #pragma unroll
                for (int mt = 0; mt < 2; mt++)
                    mma_tf32(acc[mt][nt], af[mt], b0, b1);
            }
        }

        if (ch + 1 < NCH) {
            const int nb = buf ^ 1;
            #pragma unroll
            for (int s = 0; s < 4; s++) {
                float4 wA, wB;
                wA.x = f2tf(ra[s].x); wA.y = f2tf(ra[s].y);
                wA.z = f2tf(ra[s].z); wA.w = f2tf(ra[s].w);
                wB.x = f2tf(rb[s].x); wB.y = f2tf(rb[s].y);
                wB.z = f2tf(rb[s].z); wB.w = f2tf(rb[s].w);
                *reinterpret_cast<float4*>(&As[nb][(r + s * 32) * 36 + c4]) = wA;
                *reinterpret_cast<float4*>(&Bs[nb][(r + s * 32) * 36 + c4]) = wB;
            }
        }
    }
}

// ---------------- kernel 1: QKV projections --------------------------------
__global__ __launch_bounds__(256, 2) void qkv_kernel(const float* __restrict__ x,
                                                     const float* __restrict__ wq,
                                                     const float* __restrict__ wk,
                                                     const float* __restrict__ wv) {
    extern __shared__ float dsm[];
    const int which = blockIdx.z;
    const float* W = (which == 0) ? wq : (which == 1) ? wk : wv;
    float* out = (which == 0) ? g_Q : (which == 1) ? g_K : g_V;

    const int rb = blockIdx.x * 128;
    const int cb = blockIdx.y * 128;
    float acc[2][8][4] = {};
    gemm128_db(x + (size_t)rb * DMODEL, DMODEL,
               W + (size_t)cb * DMODEL, DMODEL, acc, dsm);

    const int tid = threadIdx.x, warp = tid >> 5, lane = tid & 31;
    const int wm = warp >> 1, wn = warp & 1, g = lane >> 2, c = lane & 3;
    #pragma unroll
    for (int mt = 0; mt < 2; mt++)
        #pragma unroll
        for (int nt = 0; nt < 8; nt++)
            #pragma unroll
            for (int i = 0; i < 4; i++) {
                const int s = rb + acc_row(wm, mt, g, i);
                const int p = cb + acc_col(wn, nt, c, i);
                const int h = p >> 7, dh = p & 127;
                out[(size_t)h * SQ * DHEAD + (size_t)s * DHEAD + dh] = acc[mt][nt][i];
            }
}

// ---------------- kernel 2: RoPE in-place on Q and K ------------------------
__global__ void rope_kernel(const float* __restrict__ cosb,
                            const float* __restrict__ sinb) {
    const int t = blockIdx.x * blockDim.x + threadIdx.x;
    const int d  = t & 63;
    const int s  = (t >> 6) & (SQ - 1);
    const int h  = (t >> 17) & (NH - 1);
    const int qk = t >> 21;
    float* p = (qk ? g_K : g_Q) + (size_t)h * SQ * DHEAD + (size_t)s * DHEAD;
    const float x0 = p[d], x1 = p[d + 64];
    const float c0 = cosb[s * DHEAD + d],      s0 = sinb[s * DHEAD + d];
    const float c1 = cosb[s * DHEAD + d + 64], s1 = sinb[s * DHEAD + d + 64];
    p[d]      = x0 * c0 - x1 * s0;
    p[d + 64] = x1 * c1 + x0 * s1;
}

// ---------------- kernel 3: flash attention (fused S/softmax/PV) ------------
__global__ __launch_bounds__(256) void flash_kernel() {
    extern __shared__ float sm[];
    float* Qs      = sm;
    float* Ps      = Qs + 128 * PS_LD;
    float* Bs      = Ps + 128 * PS_LD;
    float* m_state = Bs + 128 * BS_LD;
    float* l_state = m_state + 128;
    float* rmax    = l_state + 128;
    float* rsum    = rmax + 256;

    const int bid = blockIdx.x;
    const int qt  = 15 - (bid >> 4);
    const int h   = bid & 15;
    const int rb  = qt * 128;

    const int tid = threadIdx.x, warp = tid >> 5, lane = tid & 31;
    const int wm = warp >> 1, wn = warp & 1, g = lane >> 2, c = lane & 3;
    const int m0b = wm * 32;

    if (tid < 128) { m_state[tid] = -1e30f; l_state[tid] = 0.f; }

    {
        const float* Qg = g_Q + (size_t)h * SQ * DHEAD + (size_t)rb * DHEAD;
        const int r = tid >> 3, c4 = (tid & 7) << 2;
        #pragma unroll
        for (int s = 0; s < 4; s++)
            #pragma unroll
            for (int cc = 0; cc < 4; cc++) {
                const int row = r + s * 32, col = c4 + cc * 32;
                const float4 v = *reinterpret_cast<const float4*>(
                    &Qg[(size_t)row * DHEAD + col]);
                float4 w;
                w.x = f2tf(v.x); w.y = f2tf(v.y); w.z = f2tf(v.z); w.w = f2tf(v.w);
                *reinterpret_cast<float4*>(&Qs[row * PS_LD + col]) = w;
            }
    }
    __syncthreads();

    float acc_o[2][8][4] = {};

    for (int kt = 0; kt <= qt; kt++) {
        const int cb = kt * 128;
        const float* Kg = g_K + (size_t)h * SQ * DHEAD + (size_t)cb * DHEAD;
        float acc[2][8][4] = {};

        for (int k0 = 0; k0 < DHEAD; k0 += 32) {
            const int r = tid >> 3, c4 = (tid & 7) << 2;
            #pragma unroll
            for (int s = 0; s < 4; s++) {
                const int row = r + s * 32;
                const float4 v = *reinterpret_cast<const float4*>(
                    &Kg[(size_t)row * DHEAD + k0 + c4]);
                float4 w;
                w.x = f2tf(v.x); w.y = f2tf(v.y); w.z = f2tf(v.z); w.w = f2tf(v.w);
                *reinterpret_cast<float4*>(&Bs[row * BS_LD + c4]) = w;
            }
            __syncthreads();
            #pragma unroll
            for (int kk = 0; kk < 32; kk += 8) {
                uint32_t af[2][4];
                #pragma unroll
                for (int mt = 0; mt < 2; mt++) {
                    const float* q0 = &Qs[(m0b + mt * 16 + g) * PS_LD + k0 + kk + c];
                    af[mt][0] = __float_as_uint(q0[0]);
                    af[mt][1] = __float_as_uint(q0[8 * PS_LD]);
                    af[mt][2] = __float_as_uint(q0[4]);
                    af[mt][3] = __float_as_uint(q0[8 * PS_LD + 4]);
                }
                #pragma unroll
                for (int nt = 0; nt < 8; nt++) {
                    const int n0 = wn * 64 + nt * 8;
                    const uint32_t b0 = __float_as_uint(Bs[(n0 + g) * BS_LD + kk + c]);
                    const uint32_t b1 = __float_as_uint(Bs[(n0 + g) * BS_LD + kk + c + 4]);
                    #pragma unroll
                    for (int mt = 0; mt < 2; mt++)
                        mma_tf32(acc[mt][nt], af[mt], b0, b1);
                }
            }
            __syncthreads();
        }

        float pmax[2][2] = {{-1e30f, -1e30f}, {-1e30f, -1e30f}};
        #pragma unroll
        for (int mt = 0; mt < 2; mt++)
            #pragma unroll
            for (int nt = 0; nt < 8; nt++)
                #pragma unroll
                for (int i = 0; i < 4; i++) {
                    float v = acc[mt][nt][i] * 0.08838834764831845f;
                    v = fast_tanh(v * 0.02f) * 50.0f;
                    if (kt == qt) {
                        const int rr = acc_row(wm, mt, g, i);
                        const int cl = acc_col(wn, nt, c, i);
                        if (cl > rr) v = -1e30f;
                    }
                    acc[mt][nt][i] = v;
                    pmax[mt][i >> 1] = fmaxf(pmax[mt][i >> 1], v);
                }
        #pragma unroll
        for (int mt = 0; mt < 2; mt++)
            #pragma unroll
            for (int rh = 0; rh < 2; rh++) {
                float p = pmax[mt][rh];
                p = fmaxf(p, __shfl_xor_sync(0xffffffffu, p, 1));
                p = fmaxf(p, __shfl_xor_sync(0xffffffffu, p, 2));
                pmax[mt][rh] = p;
            }
        if (c == 0) {
            #pragma unroll
            for (int mt = 0; mt < 2; mt++)
                #pragma unroll
                for (int rh = 0; rh < 2; rh++)
                    rmax[wn * 128 + m0b + mt * 16 + rh * 8 + g] = pmax[mt][rh];
        }
        __syncthreads();

        float mnew[2][2], scal[2][2], psum[2][2] = {};
        #pragma unroll
        for (int mt = 0; mt < 2; mt++)
            #pragma unroll
            for (int rh = 0; rh < 2; rh++) {
                const int r = m0b + mt * 16 + rh * 8 + g;
                const float mo = m_state[r];
                const float tm = fmaxf(rmax[r], rmax[128 + r]);
                const float mn = fmaxf(mo, tm);
                mnew[mt][rh] = mn;
                scal[mt][rh] = __expf(mo - mn);
            }
        #pragma unroll
        for (int mt = 0; mt < 2; mt++)
            #pragma unroll
            for (int nt = 0; nt < 8; nt++)
                #pragma unroll
                for (int i = 0; i < 4; i++) {
                    const int rr = acc_row(wm, mt, g, i);
                    const int cl = acc_col(wn, nt, c, i);
                    const float p = __expf(acc[mt][nt][i] - mnew[mt][i >> 1]);
                    psum[mt][i >> 1] += p;
                    Ps[rr * PS_LD + cl] = f2tf(p);
                }
        #pragma unroll
        for (int mt = 0; mt < 2; mt++)
            #pragma unroll
            for (int rh = 0; rh < 2; rh++) {
                float p = psum[mt][rh];
                p += __shfl_xor_sync(0xffffffffu, p, 1);
                p += __shfl_xor_sync(0xffffffffu, p, 2);
                psum[mt][rh] = p;
            }
        if (c == 0) {
            #pragma unroll
            for (int mt = 0; mt < 2; mt++)
                #pragma unroll
                for (int rh = 0; rh < 2; rh++)
                    rsum[wn * 128 + m0b + mt * 16 + rh * 8 + g] = psum[mt][rh];
        }
        __syncthreads();

        if (wn == 0 && c == 0) {
            #pragma unroll
            for (int mt = 0; mt < 2; mt++)
                #pragma unroll
                for (int rh = 0; rh < 2; rh++) {
                    const int r = m0b + mt * 16 + rh * 8 + g;
                    l_state[r] = l_state[r] * scal[mt][rh] + rsum[r] + rsum[128 + r];
                    m_state[r] = mnew[mt][rh];
                }
        }
        #pragma unroll
        for (int mt = 0; mt < 2; mt++)
            #pragma unroll
            for (int nt = 0; nt < 8; nt++)
                #pragma unroll
                for (int i = 0; i < 4; i++)
                    acc_o[mt][nt][i] *= scal[mt][i >> 1];

        const float* Vg = g_V + (size_t)h * SQ * DHEAD + (size_t)cb * DHEAD;
        for (int k0 = 0; k0 < 128; k0 += 32) {
            const int kr = tid >> 5, n4 = (tid & 31) << 2;
            #pragma unroll
            for (int s = 0; s < 4; s++) {
                const int kk = kr + s * 8;
                const float4 v = *reinterpret_cast<const float4*>(
                    &Vg[(size_t)(k0 + kk) * DHEAD + n4]);
                Bs[(n4 + 0) * BS_LD + kk] = f2tf(v.x);
                Bs[(n4 + 1) * BS_LD + kk] = f2tf(v.y);
                Bs[(n4 + 2) * BS_LD + kk] = f2tf(v.z);
                Bs[(n4 + 3) * BS_LD + kk] = f2tf(v.w);
            }
            __syncthreads();
            #pragma unroll
            for (int kk = 0; kk < 32; kk += 8) {
                uint32_t af[2][4];
                #pragma unroll
                for (int mt = 0; mt < 2; mt++) {
                    const float* p0 = &Ps[(m0b + mt * 16 + g) * PS_LD + k0 + kk + c];
                    af[mt][0] = __float_as_uint(p0[0]);
                    af[mt][1] = __float_as_uint(p0[8 * PS_LD]);
                    af[mt][2] = __float_as_uint(p0[4]);
                    af[mt][3] = __float_as_uint(p0[8 * PS_LD + 4]);
                }
                #pragma unroll
                for (int nt = 0; nt < 8; nt++) {
                    const int n0 = wn * 64 + nt * 8;
                    const uint32_t b0 = __float_as_uint(Bs[(n0 + g) * BS_LD + kk + c]);
                    const uint32_t b1 = __float_as_uint(Bs[(n0 + g) * BS_LD + kk + c + 4]);
                    #pragma unroll
                    for (int mt = 0; mt < 2; mt++)
                        mma_tf32(acc_o[mt][nt], af[mt], b0, b1);
                }
            }
            __syncthreads();
        }
    }

    float inv[2][2];
    #pragma unroll
    for (int mt = 0; mt < 2; mt++)
        #pragma unroll
        for (int rh = 0; rh < 2; rh++)
            inv[mt][rh] = 1.0f / l_state[m0b + mt * 16 + rh * 8 + g];
    #pragma unroll
    for (int mt = 0; mt < 2; mt++)
        #pragma unroll
        for (int nt = 0; nt < 8; nt++)
            #pragma unroll
            for (int i = 0; i < 4; i++) {
                const int q  = rb + acc_row(wm, mt, g, i);
                const int dh = acc_col(wn, nt, c, i);
                g_attn[(size_t)q * DMODEL + h * DHEAD + dh] =
                    acc_o[mt][nt][i] * inv[mt][i >> 1];
            }
}

// ---------------- kernel 4: output projection -------------------------------
__global__ __launch_bounds__(256, 2) void oproj_kernel(const float* __restrict__ wo,
                                                       float* __restrict__ out) {
    extern __shared__ float dsm[];
    const int rb = blockIdx.x * 128, cb = blockIdx.y * 128;
    float acc[2][8][4] = {};
    gemm128_db(g_attn + (size_t)rb * DMODEL, DMODEL,
               wo + (size_t)cb * DMODEL, DMODEL, acc, dsm);

    const int tid = threadIdx.x, warp = tid >> 5, lane = tid & 31;
    const int wm = warp >> 1, wn = warp & 1, g = lane >> 2, c = lane & 3;
    #pragma unroll
    for (int mt = 0; mt < 2; mt++)
        #pragma unroll
        for (int nt = 0; nt < 8; nt++)
            #pragma unroll
            for (int i = 0; i < 4; i++) {
                const int s = rb + acc_row(wm, mt, g, i);
                const int d = cb + acc_col(wn, nt, c, i);
                out[(size_t)s * DMODEL + d] = acc[mt][nt][i];
            }
}

// ---------------- launch ----------------------------------------------------
extern "C" void kernel_launch(void* const* d_in, const int* in_sizes, int n_in,
                              void* d_out, int out_size) {
    (void)in_sizes; (void)n_in; (void)out_size;
    const float* x  = (const float*)d_in[0];
    const float* rc = (const float*)d_in[1];
    const float* rs = (const float*)d_in[2];
    const float* wq = (const float*)d_in[4];
    const float* wk = (const float*)d_in[5];
    const float* wv = (const float*)d_in[6];
    const float* wo = (const float*)d_in[7];
    float* out = (float*)d_out;

    const int dense_smem = DENSE_SMEM_F * (int)sizeof(float);   // 72 KB
    const int flash_smem = (2 * 128 * PS_LD + 128 * BS_LD + 6 * 128) * (int)sizeof(float);
    cudaFuncSetAttribute(flash_kernel,
                         cudaFuncAttributeMaxDynamicSharedMemorySize, flash_smem);
    cudaFuncSetAttribute(qkv_kernel,
                         cudaFuncAttributeMaxDynamicSharedMemorySize, dense_smem);
    cudaFuncSetAttribute(oproj_kernel,
                         cudaFuncAttributeMaxDynamicSharedMemorySize, dense_smem);

    qkv_kernel<<<dim3(16, 16, 3), 256, dense_smem>>>(x, wq, wk, wv);
    rope_kernel<<<16384, 256>>>(rc, rs);
    flash_kernel<<<256, 256, flash_smem>>>();
    oproj_kernel<<<dim3(16, 16), 256, dense_smem>>>(wo, out);
}

// round 5
// speedup vs baseline: 1.3886x; 1.0703x over previous
#include <cuda_runtime.h>
#include <cstdint>
#include <cstddef>

#define SQ 2048
#define DMODEL 2048
#define NH 16
#define DHEAD 128
#define NCH (DMODEL / 32)

#define DPAD 40                  // dense smem tile stride (floats); 40%32==8 -> conflict-free float2
#define DTILE_F (128 * DPAD)     // 5120 floats per tile
#define QLD 136                  // flash Q/P stride; 136%32==8
#define VLD 132                  // flash V slice stride; 132%32==4 (scalar loads, conflict-free)
#define KPAD 40                  // flash K slice stride

// ---------------- scratch (static device globals; no runtime allocation) ----
__device__ float g_Q[NH * SQ * DHEAD];
__device__ float g_K[NH * SQ * DHEAD];
__device__ float g_V[NH * SQ * DHEAD];
__device__ float g_attn[SQ * DMODEL];
__device__ float g_rx[SQ * DMODEL];
__device__ float g_rwq[SQ * DMODEL];
__device__ float g_rwk[SQ * DMODEL];
__device__ float g_rwv[SQ * DMODEL];
__device__ float g_rwo[SQ * DMODEL];

// ---------------- helpers ---------------------------------------------------
__device__ __forceinline__ float f2tf(float f) {
    uint32_t r;
    asm("cvt.rna.tf32.f32 %0, %1;" : "=r"(r) : "f"(f));
    return __uint_as_float(r);
}

__device__ __forceinline__ float fast_tanh(float x) {
    const float e = __expf(2.0f * x);
    return 1.0f - 2.0f / (e + 1.0f);
}

__device__ __forceinline__ uint32_t s2u(const void* p) {
    uint32_t a;
    asm("{ .reg .u64 t; cvta.to.shared.u64 t, %1; cvt.u32.u64 %0, t; }"
        : "=r"(a) : "l"(p));
    return a;
}

__device__ __forceinline__ void cp16(uint32_t s, const void* g) {
    asm volatile("cp.async.ca.shared.global [%0], [%1], 16;" :: "r"(s), "l"(g) : "memory");
}
__device__ __forceinline__ void cp_commit() {
    asm volatile("cp.async.commit_group;" ::: "memory");
}
template <int N>
__device__ __forceinline__ void cp_wait() {
    asm volatile("cp.async.wait_group %0;" :: "n"(N) : "memory");
}

__device__ __forceinline__ void mma_tf32(float acc[4], const uint32_t a[4],
                                         uint32_t b0, uint32_t b1) {
    asm volatile(
        "mma.sync.aligned.m16n8k8.row.col.f32.tf32.tf32.f32 "
        "{%0,%1,%2,%3}, {%4,%5,%6,%7}, {%8,%9}, {%0,%1,%2,%3};\n"
        : "+f"(acc[0]), "+f"(acc[1]), "+f"(acc[2]), "+f"(acc[3])
        : "r"(a[0]), "r"(a[1]), "r"(a[2]), "r"(a[3]), "r"(b0), "r"(b1));
}

__device__ __forceinline__ int acc_row(int wm, int mt, int g, int i) {
    return wm * 32 + mt * 16 + g + ((i >> 1) << 3);
}
__device__ __forceinline__ int acc_col(int wn, int nt, int c, int i) {
    return wn * 64 + nt * 8 + c * 2 + (i & 1);
}

// ---------------- kernel 0: pre-round fp32 -> tf32-exact fp32 ---------------
__global__ void preround_kernel(const float* __restrict__ src, float* __restrict__ dst) {
    const int i = blockIdx.x * blockDim.x + threadIdx.x;
    float4 v = reinterpret_cast<const float4*>(src)[i];
    v.x = f2tf(v.x); v.y = f2tf(v.y); v.z = f2tf(v.z); v.w = f2tf(v.w);
    reinterpret_cast<float4*>(dst)[i] = v;
}

// ---------------- dense GEMM core: 128x128 tile, cp.async double-buffered ---
// A, B pre-rounded tf32-exact fp32, K-major. C = A * B^T.
// k-permutation: mma slot c <- logical k = kk+2c, slot c+4 <- kk+2c+1 (A and B
// use identical mapping, so the k-sum is unchanged) -> all frag loads LDS.64.
__device__ __forceinline__ void gemm128(const float* __restrict__ A, int lda,
                                        const float* __restrict__ B, int ldb,
                                        float acc[2][8][4], float* sm) {
    const int tid = threadIdx.x, warp = tid >> 5, lane = tid & 31;
    const int wm = warp >> 1, wn = warp & 1, g = lane >> 2, c = lane & 3;
    const int r = tid >> 3, c4 = (tid & 7) << 2;
    const uint32_t sb = s2u(sm);

    // stage chunk k0 into buffer `buf`
    auto stage = [&](int buf, int k0) {
        const uint32_t abase = sb + (buf ? DTILE_F : 0) * 4;
        const uint32_t bbase = sb + ((buf ? 3 : 2) * DTILE_F) * 4;
        #pragma unroll
        for (int s = 0; s < 4; s++) {
            const int row = r + s * 32;
            cp16(abase + (row * DPAD + c4) * 4, &A[(size_t)row * lda + k0 + c4]);
            cp16(bbase + (row * DPAD + c4) * 4, &B[(size_t)row * ldb + k0 + c4]);
        }
    };

    stage(0, 0);
    cp_commit();

    for (int ch = 0; ch < NCH; ch++) {
        const int buf = ch & 1;
        if (ch + 1 < NCH) {
            stage(buf ^ 1, (ch + 1) * 32);
            cp_commit();
            cp_wait<1>();
        } else {
            cp_wait<0>();
        }
        __syncthreads();

        const float* Ab = sm + (buf ? DTILE_F : 0);
        const float* Bb = sm + (buf ? 3 : 2) * DTILE_F;
        #pragma unroll
        for (int kk = 0; kk < 32; kk += 8) {
            uint32_t af[2][4];
            #pragma unroll
            for (int mt = 0; mt < 2; mt++) {
                const int m0 = wm * 32 + mt * 16 + g;
                const float2 p0 = *reinterpret_cast<const float2*>(&Ab[m0 * DPAD + kk + 2 * c]);
                const float2 p1 = *reinterpret_cast<const float2*>(&Ab[(m0 + 8) * DPAD + kk + 2 * c]);
                af[mt][0] = __float_as_uint(p0.x); af[mt][2] = __float_as_uint(p0.y);
                af[mt][1] = __float_as_uint(p1.x); af[mt][3] = __float_as_uint(p1.y);
            }
            #pragma unroll
            for (int nt = 0; nt < 8; nt++) {
                const float2 bb = *reinterpret_cast<const float2*>(
                    &Bb[(wn * 64 + nt * 8 + g) * DPAD + kk + 2 * c]);
                const uint32_t b0 = __float_as_uint(bb.x);
                const uint32_t b1 = __float_as_uint(bb.y);
                #pragma unroll
                for (int mt = 0; mt < 2; mt++)
                    mma_tf32(acc[mt][nt], af[mt], b0, b1);
            }
        }
        __syncthreads();
    }
}

// ---------------- kernel 1: QKV projections --------------------------------
__global__ __launch_bounds__(256, 2) void qkv_kernel() {
    extern __shared__ float dsm[];
    const int which = blockIdx.z;
    const float* W = (which == 0) ? g_rwq : (which == 1) ? g_rwk : g_rwv;
    float* out = (which == 0) ? g_Q : (which == 1) ? g_K : g_V;

    const int rb = blockIdx.x * 128;
    const int cb = blockIdx.y * 128;
    float acc[2][8][4] = {};
    gemm128(g_rx + (size_t)rb * DMODEL, DMODEL,
            W + (size_t)cb * DMODEL, DMODEL, acc, dsm);

    const int tid = threadIdx.x, warp = tid >> 5, lane = tid & 31;
    const int wm = warp >> 1, wn = warp & 1, g = lane >> 2, c = lane & 3;
    const bool roundV = (which == 2);   // V feeds attention directly: store tf32-exact
    #pragma unroll
    for (int mt = 0; mt < 2; mt++)
        #pragma unroll
        for (int nt = 0; nt < 8; nt++)
            #pragma unroll
            for (int i = 0; i < 4; i++) {
                const int s = rb + acc_row(wm, mt, g, i);
                const int p = cb + acc_col(wn, nt, c, i);
                const int h = p >> 7, dh = p & 127;
                const float v = roundV ? f2tf(acc[mt][nt][i]) : acc[mt][nt][i];
                out[(size_t)h * SQ * DHEAD + (size_t)s * DHEAD + dh] = v;
            }
}

// ---------------- kernel 2: RoPE in-place, stores tf32-exact ----------------
__global__ void rope_kernel(const float* __restrict__ cosb,
                            const float* __restrict__ sinb) {
    const int t = blockIdx.x * blockDim.x + threadIdx.x;
    const int d  = t & 63;
    const int s  = (t >> 6) & (SQ - 1);
    const int h  = (t >> 17) & (NH - 1);
    const int qk = t >> 21;
    float* p = (qk ? g_K : g_Q) + (size_t)h * SQ * DHEAD + (size_t)s * DHEAD;
    const float x0 = p[d], x1 = p[d + 64];
    const float c0 = cosb[s * DHEAD + d],      s0 = sinb[s * DHEAD + d];
    const float c1 = cosb[s * DHEAD + d + 64], s1 = sinb[s * DHEAD + d + 64];
    p[d]      = f2tf(x0 * c0 - x1 * s0);
    p[d + 64] = f2tf(x1 * c1 + x0 * s1);
}

// ---------------- kernel 3: flash attention ---------------------------------
// smem floats: Qs[128*QLD], Ps[128*QLD], KV[DTILE_F], m[128], l[128], rmax[256], rsum[256]
#define FL_QS 0
#define FL_PS (128 * QLD)
#define FL_KV (2 * 128 * QLD)
#define FL_M  (FL_KV + DTILE_F)
#define FL_L  (FL_M + 128)
#define FL_RMAX (FL_L + 128)
#define FL_RSUM (FL_RMAX + 256)
#define FL_TOT  (FL_RSUM + 256)

__global__ __launch_bounds__(256) void flash_kernel() {
    extern __shared__ float sm[];
    float* Qs = sm + FL_QS;
    float* Ps = sm + FL_PS;
    float* KV = sm + FL_KV;
    float* m_state = sm + FL_M;
    float* l_state = sm + FL_L;
    float* rmax = sm + FL_RMAX;
    float* rsum = sm + FL_RSUM;
    const uint32_t kvb = s2u(KV);

    const int bid = blockIdx.x;
    const int qt  = 15 - (bid >> 4);
    const int h   = bid & 15;
    const int rb  = qt * 128;

    const int tid = threadIdx.x, warp = tid >> 5, lane = tid & 31;
    const int wm = warp >> 1, wn = warp & 1, g = lane >> 2, c = lane & 3;
    const int m0b = wm * 32;
    const int r = tid >> 3, c4 = (tid & 7) << 2;

    if (tid < 128) { m_state[tid] = -1e30f; l_state[tid] = 0.f; }

    // Q tile (already tf32-exact from rope): raw copy
    {
        const float* Qg = g_Q + (size_t)h * SQ * DHEAD + (size_t)rb * DHEAD;
        #pragma unroll
        for (int s = 0; s < 4; s++)
            #pragma unroll
            for (int cc = 0; cc < 4; cc++) {
                const int row = r + s * 32, col = c4 + cc * 32;
                *reinterpret_cast<float4*>(&Qs[row * QLD + col]) =
                    *reinterpret_cast<const float4*>(&Qg[(size_t)row * DHEAD + col]);
            }
    }
    __syncthreads();

    float acc_o[2][8][4] = {};

    for (int kt = 0; kt <= qt; kt++) {
        const int cb = kt * 128;
        const float* Kg = g_K + (size_t)h * SQ * DHEAD + (size_t)cb * DHEAD;
        float acc[2][8][4] = {};

        // ---- S = Q @ K^T : K slices via cp.async, KV stride KPAD ----
        for (int k0 = 0; k0 < DHEAD; k0 += 32) {
            #pragma unroll
            for (int s = 0; s < 4; s++) {
                const int row = r + s * 32;
                cp16(kvb + (row * KPAD + c4) * 4, &Kg[(size_t)row * DHEAD + k0 + c4]);
            }
            cp_commit();
            cp_wait<0>();
            __syncthreads();
            #pragma unroll
            for (int kk = 0; kk < 32; kk += 8) {
                uint32_t af[2][4];
                #pragma unroll
                for (int mt = 0; mt < 2; mt++) {
                    const int m0 = m0b + mt * 16 + g;
                    const float2 q0 = *reinterpret_cast<const float2*>(
                        &Qs[m0 * QLD + k0 + kk + 2 * c]);
                    const float2 q1 = *reinterpret_cast<const float2*>(
                        &Qs[(m0 + 8) * QLD + k0 + kk + 2 * c]);
                    af[mt][0] = __float_as_uint(q0.x); af[mt][2] = __float_as_uint(q0.y);
                    af[mt][1] = __float_as_uint(q1.x); af[mt][3] = __float_as_uint(q1.y);
                }
                #pragma unroll
                for (int nt = 0; nt < 8; nt++) {
                    const float2 bb = *reinterpret_cast<const float2*>(
                        &KV[(wn * 64 + nt * 8 + g) * KPAD + kk + 2 * c]);
                    const uint32_t b0 = __float_as_uint(bb.x);
                    const uint32_t b1 = __float_as_uint(bb.y);
                    #pragma unroll
                    for (int mt = 0; mt < 2; mt++)
                        mma_tf32(acc[mt][nt], af[mt], b0, b1);
                }
            }
            __syncthreads();
        }

        // ---- softcap + mask + row max ----
        float pmax[2][2] = {{-1e30f, -1e30f}, {-1e30f, -1e30f}};
        #pragma unroll
        for (int mt = 0; mt < 2; mt++)
            #pragma unroll
            for (int nt = 0; nt < 8; nt++)
                #pragma unroll
                for (int i = 0; i < 4; i++) {
                    float v = acc[mt][nt][i] * 0.08838834764831845f;
                    v = fast_tanh(v * 0.02f) * 50.0f;
                    if (kt == qt) {
                        const int rr = acc_row(wm, mt, g, i);
                        const int cl = acc_col(wn, nt, c, i);
                        if (cl > rr) v = -1e30f;
                    }
                    acc[mt][nt][i] = v;
                    pmax[mt][i >> 1] = fmaxf(pmax[mt][i >> 1], v);
                }
        #pragma unroll
        for (int mt = 0; mt < 2; mt++)
            #pragma unroll
            for (int rh = 0; rh < 2; rh++) {
                float p = pmax[mt][rh];
                p = fmaxf(p, __shfl_xor_sync(0xffffffffu, p, 1));
                p = fmaxf(p, __shfl_xor_sync(0xffffffffu, p, 2));
                pmax[mt][rh] = p;
            }
        if (c == 0) {
            #pragma unroll
            for (int mt = 0; mt < 2; mt++)
                #pragma unroll
                for (int rh = 0; rh < 2; rh++)
                    rmax[wn * 128 + m0b + mt * 16 + rh * 8 + g] = pmax[mt][rh];
        }
        __syncthreads();

        // ---- m_new, P = exp(v - m_new) -> Ps (tf32-exact), row sums ----
        float mnew[2][2], scal[2][2], psum[2][2] = {};
        #pragma unroll
        for (int mt = 0; mt < 2; mt++)
            #pragma unroll
            for (int rh = 0; rh < 2; rh++) {
                const int rr = m0b + mt * 16 + rh * 8 + g;
                const float mo = m_state[rr];
                const float tm = fmaxf(rmax[rr], rmax[128 + rr]);
                const float mn = fmaxf(mo, tm);
                mnew[mt][rh] = mn;
                scal[mt][rh] = __expf(mo - mn);
            }
        #pragma unroll
        for (int mt = 0; mt < 2; mt++)
            #pragma unroll
            for (int nt = 0; nt < 8; nt++)
                #pragma unroll
                for (int i = 0; i < 4; i++) {
                    const int rr = acc_row(wm, mt, g, i);
                    const int cl = acc_col(wn, nt, c, i);
                    const float p = __expf(acc[mt][nt][i] - mnew[mt][i >> 1]);
                    psum[mt][i >> 1] += p;
                    Ps[rr * QLD + cl] = f2tf(p);
                }
        #pragma unroll
        for (int mt = 0; mt < 2; mt++)
            #pragma unroll
            for (int rh = 0; rh < 2; rh++) {
                float p = psum[mt][rh];
                p += __shfl_xor_sync(0xffffffffu, p, 1);
                p += __shfl_xor_sync(0xffffffffu, p, 2);
                psum[mt][rh] = p;
            }
        if (c == 0) {
            #pragma unroll
            for (int mt = 0; mt < 2; mt++)
                #pragma unroll
                for (int rh = 0; rh < 2; rh++)
                    rsum[wn * 128 + m0b + mt * 16 + rh * 8 + g] = psum[mt][rh];
        }
        __syncthreads();

        if (wn == 0 && c == 0) {
            #pragma unroll
            for (int mt = 0; mt < 2; mt++)
                #pragma unroll
                for (int rh = 0; rh < 2; rh++) {
                    const int rr = m0b + mt * 16 + rh * 8 + g;
                    l_state[rr] = l_state[rr] * scal[mt][rh] + rsum[rr] + rsum[128 + rr];
                    m_state[rr] = mnew[mt][rh];
                }
        }
        #pragma unroll
        for (int mt = 0; mt < 2; mt++)
            #pragma unroll
            for (int nt = 0; nt < 8; nt++)
                #pragma unroll
                for (int i = 0; i < 4; i++)
                    acc_o[mt][nt][i] *= scal[mt][i >> 1];

        // ---- O += P @ V : V slices natural layout via cp.async, stride VLD ----
        const float* Vg = g_V + (size_t)h * SQ * DHEAD + (size_t)cb * DHEAD;
        for (int k0 = 0; k0 < 128; k0 += 32) {
            #pragma unroll
            for (int s = 0; s < 4; s++) {
                const int idx = s * 256 + tid;
                const int row = idx >> 5;         // 0..31 (seq within slice)
                const int cf  = (idx & 31) << 2;  // 0..124 (dh)
                cp16(kvb + (row * VLD + cf) * 4, &Vg[(size_t)(k0 + row) * DHEAD + cf]);
            }
            cp_commit();
            cp_wait<0>();
            __syncthreads();
            #pragma unroll
            for (int kk = 0; kk < 32; kk += 8) {
                uint32_t af[2][4];
                #pragma unroll
                for (int mt = 0; mt < 2; mt++) {
                    const int m0 = m0b + mt * 16 + g;
                    const float2 p0 = *reinterpret_cast<const float2*>(
                        &Ps[m0 * QLD + k0 + kk + 2 * c]);
                    const float2 p1 = *reinterpret_cast<const float2*>(
                        &Ps[(m0 + 8) * QLD + k0 + kk + 2 * c]);
                    af[mt][0] = __float_as_uint(p0.x); af[mt][2] = __float_as_uint(p0.y);
                    af[mt][1] = __float_as_uint(p1.x); af[mt][3] = __float_as_uint(p1.y);
                }
                #pragma unroll
                for (int nt = 0; nt < 8; nt++) {
                    const int n0 = wn * 64 + nt * 8 + g;
                    const uint32_t b0 = __float_as_uint(KV[(kk + 2 * c) * VLD + n0]);
                    const uint32_t b1 = __float_as_uint(KV[(kk + 2 * c + 1) * VLD + n0]);
                    #pragma unroll
                    for (int mt = 0; mt < 2; mt++)
                        mma_tf32(acc_o[mt][nt], af[mt], b0, b1);
                }
            }
            __syncthreads();
        }
    }

    // ---- normalize + store tf32-exact (feeds oproj A) ----
    float inv[2][2];
    #pragma unroll
    for (int mt = 0; mt < 2; mt++)
        #pragma unroll
        for (int rh = 0; rh < 2; rh++)
            inv[mt][rh] = 1.0f / l_state[m0b + mt * 16 + rh * 8 + g];
    #pragma unroll
    for (int mt = 0; mt < 2; mt++)
        #pragma unroll
        for (int nt = 0; nt < 8; nt++)
            #pragma unroll
            for (int i = 0; i < 4; i++) {
                const int q  = rb + acc_row(wm, mt, g, i);
                const int dh = acc_col(wn, nt, c, i);
                g_attn[(size_t)q * DMODEL + h * DHEAD + dh] =
                    f2tf(acc_o[mt][nt][i] * inv[mt][i >> 1]);
            }
}

// ---------------- kernel 4: output projection -------------------------------
__global__ __launch_bounds__(256, 2) void oproj_kernel(float* __restrict__ out) {
    extern __shared__ float dsm[];
    const int rb = blockIdx.x * 128, cb = blockIdx.y * 128;
    float acc[2][8][4] = {};
    gemm128(g_attn + (size_t)rb * DMODEL, DMODEL,
            g_rwo + (size_t)cb * DMODEL, DMODEL, acc, dsm);

    const int tid = threadIdx.x, warp = tid >> 5, lane = tid & 31;
    const int wm = warp >> 1, wn = warp & 1, g = lane >> 2, c = lane & 3;
    #pragma unroll
    for (int mt = 0; mt < 2; mt++)
        #pragma unroll
        for (int nt = 0; nt < 8; nt++)
            #pragma unroll
            for (int i = 0; i < 4; i++) {
                const int s = rb + acc_row(wm, mt, g, i);
                const int d = cb + acc_col(wn, nt, c, i);
                out[(size_t)s * DMODEL + d] = acc[mt][nt][i];
            }
}

// ---------------- launch ----------------------------------------------------
extern "C" void kernel_launch(void* const* d_in, const int* in_sizes, int n_in,
                              void* d_out, int out_size) {
    (void)in_sizes; (void)n_in; (void)out_size;
    const float* x  = (const float*)d_in[0];
    const float* rc = (const float*)d_in[1];
    const float* rs = (const float*)d_in[2];
    const float* wq = (const float*)d_in[4];
    const float* wk = (const float*)d_in[5];
    const float* wv = (const float*)d_in[6];
    const float* wo = (const float*)d_in[7];
    float* out = (float*)d_out;

    float *d_rx, *d_rwq, *d_rwk, *d_rwv, *d_rwo;
    cudaGetSymbolAddress((void**)&d_rx,  g_rx);
    cudaGetSymbolAddress((void**)&d_rwq, g_rwq);
    cudaGetSymbolAddress((void**)&d_rwk, g_rwk);
    cudaGetSymbolAddress((void**)&d_rwv, g_rwv);
    cudaGetSymbolAddress((void**)&d_rwo, g_rwo);

    const int dense_smem = 4 * DTILE_F * (int)sizeof(float);   // 80 KB
    const int flash_smem = FL_TOT * (int)sizeof(float);        // ~163 KB
    cudaFuncSetAttribute(flash_kernel,
                         cudaFuncAttributeMaxDynamicSharedMemorySize, flash_smem);
    cudaFuncSetAttribute(qkv_kernel,
                         cudaFuncAttributeMaxDynamicSharedMemorySize, dense_smem);
    cudaFuncSetAttribute(oproj_kernel,
                         cudaFuncAttributeMaxDynamicSharedMemorySize, dense_smem);

    const int prb = (SQ * DMODEL / 4) / 256;   // 4096 blocks per 16MB array
    preround_kernel<<<prb, 256>>>(x,  d_rx);
    preround_kernel<<<prb, 256>>>(wq, d_rwq);
    preround_kernel<<<prb, 256>>>(wk, d_rwk);
    preround_kernel<<<prb, 256>>>(wv, d_rwv);
    preround_kernel<<<prb, 256>>>(wo, d_rwo);

    qkv_kernel<<<dim3(16, 16, 3), 256, dense_smem>>>();
    rope_kernel<<<16384, 256>>>(rc, rs);
    flash_kernel<<<256, 256, flash_smem>>>();
    oproj_kernel<<<dim3(16, 16), 256, dense_smem>>>(out);
}

// round 6
// speedup vs baseline: 1.4031x; 1.0104x over previous
#include <cuda_runtime.h>
#include <cstdint>
#include <cstddef>

#define SQ 2048
#define DMODEL 2048
#define NH 16
#define DHEAD 128
#define NCH (DMODEL / 32)

#define DPAD 40                  // smem tile stride (floats); 40%32==8 -> conflict-free float2
#define ATILE_F (256 * DPAD)     // A stage: 256 rows
#define BTILE_F (128 * DPAD)     // B stage: 128 rows
#define DSM_TOT (2 * ATILE_F + 2 * BTILE_F)   // 30720 floats = 120 KB
#define QLD 136
#define VLD 132
#define KPAD 40
#define KVTILE_F (128 * KPAD)

// ---------------- scratch (static device globals; no runtime allocation) ----
__device__ float g_Q[NH * SQ * DHEAD];
__device__ float g_K[NH * SQ * DHEAD];
__device__ float g_V[NH * SQ * DHEAD];
__device__ float g_attn[SQ * DMODEL];
__device__ float g_rx[SQ * DMODEL];
__device__ float g_rwq[SQ * DMODEL];
__device__ float g_rwk[SQ * DMODEL];
__device__ float g_rwv[SQ * DMODEL];
__device__ float g_rwo[SQ * DMODEL];

// ---------------- helpers ---------------------------------------------------
__device__ __forceinline__ float f2tf(float f) {
    uint32_t r;
    asm("cvt.rna.tf32.f32 %0, %1;" : "=r"(r) : "f"(f));
    return __uint_as_float(r);
}

__device__ __forceinline__ float fast_tanh(float x) {
    const float e = __expf(2.0f * x);
    return 1.0f - 2.0f / (e + 1.0f);
}

__device__ __forceinline__ uint32_t s2u(const void* p) {
    uint32_t a;
    asm("{ .reg .u64 t; cvta.to.shared.u64 t, %1; cvt.u32.u64 %0, t; }"
        : "=r"(a) : "l"(p));
    return a;
}

__device__ __forceinline__ void cp16(uint32_t s, const void* g) {
    asm volatile("cp.async.ca.shared.global [%0], [%1], 16;" :: "r"(s), "l"(g) : "memory");
}
__device__ __forceinline__ void cp_commit() {
    asm volatile("cp.async.commit_group;" ::: "memory");
}
template <int N>
__device__ __forceinline__ void cp_wait() {
    asm volatile("cp.async.wait_group %0;" :: "n"(N) : "memory");
}

__device__ __forceinline__ void mma_tf32(float acc[4], const uint32_t a[4],
                                         uint32_t b0, uint32_t b1) {
    asm volatile(
        "mma.sync.aligned.m16n8k8.row.col.f32.tf32.tf32.f32 "
        "{%0,%1,%2,%3}, {%4,%5,%6,%7}, {%8,%9}, {%0,%1,%2,%3};\n"
        : "+f"(acc[0]), "+f"(acc[1]), "+f"(acc[2]), "+f"(acc[3])
        : "r"(a[0]), "r"(a[1]), "r"(a[2]), "r"(a[3]), "r"(b0), "r"(b1));
}

__device__ __forceinline__ int acc_row8(int wm, int mt, int g, int i) {  // 32-row warp (flash)
    return wm * 32 + mt * 16 + g + ((i >> 1) << 3);
}
__device__ __forceinline__ int acc_col8(int wn, int nt, int c, int i) {
    return wn * 64 + nt * 8 + c * 2 + (i & 1);
}

// ---------------- kernel 0: pre-round fp32 -> tf32-exact fp32 ---------------
__global__ void preround_kernel(const float* __restrict__ src, float* __restrict__ dst) {
    const int base = blockIdx.x * 1024 + threadIdx.x;
    float4 v[4];
    #pragma unroll
    for (int k = 0; k < 4; k++)
        v[k] = reinterpret_cast<const float4*>(src)[base + k * 256];
    #pragma unroll
    for (int k = 0; k < 4; k++) {
        v[k].x = f2tf(v[k].x); v[k].y = f2tf(v[k].y);
        v[k].z = f2tf(v[k].z); v[k].w = f2tf(v[k].w);
        reinterpret_cast<float4*>(dst)[base + k * 256] = v[k];
    }
}

// ---------------- dense GEMM core: 256x128 CTA tile, warp tile 64x64 --------
// A, B pre-rounded tf32-exact fp32, K-major. C = A * B^T.
// 8 warps: wm = warp>>1 (0..3, 64 rows each), wn = warp&1 (0..1, 64 cols each).
// k-permutation identical on A and B (slot c <- kk+2c, slot c+4 <- kk+2c+1).
__device__ __forceinline__ void gemm256(const float* __restrict__ A, int lda,
                                        const float* __restrict__ B, int ldb,
                                        float acc[4][8][4], float* sm) {
    const int tid = threadIdx.x, warp = tid >> 5, lane = tid & 31;
    const int wm = warp >> 1, wn = warp & 1, g = lane >> 2, c = lane & 3;
    const int r = tid >> 3, c4 = (tid & 7) << 2;
    const uint32_t sb = s2u(sm);

    auto stage = [&](int buf, int k0) {
        const uint32_t abase = sb + (buf ? ATILE_F : 0) * 4;
        const uint32_t bbase = sb + (2 * ATILE_F + (buf ? BTILE_F : 0)) * 4;
        #pragma unroll
        for (int s = 0; s < 8; s++) {
            const int row = r + s * 32;
            cp16(abase + (row * DPAD + c4) * 4, &A[(size_t)row * lda + k0 + c4]);
        }
        #pragma unroll
        for (int s = 0; s < 4; s++) {
            const int row = r + s * 32;
            cp16(bbase + (row * DPAD + c4) * 4, &B[(size_t)row * ldb + k0 + c4]);
        }
    };

    stage(0, 0);
    cp_commit();

    for (int ch = 0; ch < NCH; ch++) {
        const int buf = ch & 1;
        if (ch + 1 < NCH) {
            stage(buf ^ 1, (ch + 1) * 32);
            cp_commit();
            cp_wait<1>();
        } else {
            cp_wait<0>();
        }
        __syncthreads();

        const float* Ab = sm + (buf ? ATILE_F : 0);
        const float* Bb = sm + 2 * ATILE_F + (buf ? BTILE_F : 0);
        #pragma unroll
        for (int kk = 0; kk < 32; kk += 8) {
            uint32_t af[4][4];
            #pragma unroll
            for (int mt = 0; mt < 4; mt++) {
                const int m0 = wm * 64 + mt * 16 + g;
                const float2 p0 = *reinterpret_cast<const float2*>(&Ab[m0 * DPAD + kk + 2 * c]);
                const float2 p1 = *reinterpret_cast<const float2*>(&Ab[(m0 + 8) * DPAD + kk + 2 * c]);
                af[mt][0] = __float_as_uint(p0.x); af[mt][2] = __float_as_uint(p0.y);
                af[mt][1] = __float_as_uint(p1.x); af[mt][3] = __float_as_uint(p1.y);
            }
            #pragma unroll
            for (int nt = 0; nt < 8; nt++) {
                const float2 bb = *reinterpret_cast<const float2*>(
                    &Bb[(wn * 64 + nt * 8 + g) * DPAD + kk + 2 * c]);
                const uint32_t b0 = __float_as_uint(bb.x);
                const uint32_t b1 = __float_as_uint(bb.y);
                #pragma unroll
                for (int mt = 0; mt < 4; mt++)
                    mma_tf32(acc[mt][nt], af[mt], b0, b1);
            }
        }
        __syncthreads();
    }
}

// ---------------- kernel 1: QKV projections --------------------------------
__global__ __launch_bounds__(256, 1) void qkv_kernel() {
    extern __shared__ float dsm[];
    const int which = blockIdx.z;
    const float* W = (which == 0) ? g_rwq : (which == 1) ? g_rwk : g_rwv;
    float* out = (which == 0) ? g_Q : (which == 1) ? g_K : g_V;

    const int rb = blockIdx.x * 256;
    const int cb = blockIdx.y * 128;
    float acc[4][8][4] = {};
    gemm256(g_rx + (size_t)rb * DMODEL, DMODEL,
            W + (size_t)cb * DMODEL, DMODEL, acc, dsm);

    const int tid = threadIdx.x, warp = tid >> 5, lane = tid & 31;
    const int wm = warp >> 1, wn = warp & 1, g = lane >> 2, c = lane & 3;
    const bool roundV = (which == 2);
    #pragma unroll
    for (int mt = 0; mt < 4; mt++)
        #pragma unroll
        for (int nt = 0; nt < 8; nt++)
            #pragma unroll
            for (int i = 0; i < 4; i++) {
                const int s = rb + wm * 64 + mt * 16 + g + ((i >> 1) << 3);
                const int p = cb + wn * 64 + nt * 8 + c * 2 + (i & 1);
                const int h = p >> 7, dh = p & 127;
                const float v = roundV ? f2tf(acc[mt][nt][i]) : acc[mt][nt][i];
                out[(size_t)h * SQ * DHEAD + (size_t)s * DHEAD + dh] = v;
            }
}

// ---------------- kernel 2: RoPE in-place, stores tf32-exact ----------------
__global__ void rope_kernel(const float* __restrict__ cosb,
                            const float* __restrict__ sinb) {
    const int t = blockIdx.x * blockDim.x + threadIdx.x;
    const int d  = t & 63;
    const int s  = (t >> 6) & (SQ - 1);
    const int h  = (t >> 17) & (NH - 1);
    const int qk = t >> 21;
    float* p = (qk ? g_K : g_Q) + (size_t)h * SQ * DHEAD + (size_t)s * DHEAD;
    const float x0 = p[d], x1 = p[d + 64];
    const float c0 = cosb[s * DHEAD + d],      s0 = sinb[s * DHEAD + d];
    const float c1 = cosb[s * DHEAD + d + 64], s1 = sinb[s * DHEAD + d + 64];
    p[d]      = f2tf(x0 * c0 - x1 * s0);
    p[d + 64] = f2tf(x1 * c1 + x0 * s1);
}

// ---------------- kernel 3: flash attention ---------------------------------
#define FL_QS 0
#define FL_PS (128 * QLD)
#define FL_KV (2 * 128 * QLD)
#define FL_M  (FL_KV + KVTILE_F)
#define FL_L  (FL_M + 128)
#define FL_RMAX (FL_L + 128)
#define FL_RSUM (FL_RMAX + 256)
#define FL_TOT  (FL_RSUM + 256)

__global__ __launch_bounds__(256) void flash_kernel() {
    extern __shared__ float sm[];
    float* Qs = sm + FL_QS;
    float* Ps = sm + FL_PS;
    float* KV = sm + FL_KV;
    float* m_state = sm + FL_M;
    float* l_state = sm + FL_L;
    float* rmax = sm + FL_RMAX;
    float* rsum = sm + FL_RSUM;
    const uint32_t kvb = s2u(KV);

    const int bid = blockIdx.x;
    const int qt  = 15 - (bid >> 4);
    const int h   = bid & 15;
    const int rb  = qt * 128;

    const int tid = threadIdx.x, warp = tid >> 5, lane = tid & 31;
    const int wm = warp >> 1, wn = warp & 1, g = lane >> 2, c = lane & 3;
    const int m0b = wm * 32;
    const int r = tid >> 3, c4 = (tid & 7) << 2;

    if (tid < 128) { m_state[tid] = -1e30f; l_state[tid] = 0.f; }

    {
        const float* Qg = g_Q + (size_t)h * SQ * DHEAD + (size_t)rb * DHEAD;
        #pragma unroll
        for (int s = 0; s < 4; s++)
            #pragma unroll
            for (int cc = 0; cc < 4; cc++) {
                const int row = r + s * 32, col = c4 + cc * 32;
                *reinterpret_cast<float4*>(&Qs[row * QLD + col]) =
                    *reinterpret_cast<const float4*>(&Qg[(size_t)row * DHEAD + col]);
            }
    }
    __syncthreads();

    float acc_o[2][8][4] = {};

    for (int kt = 0; kt <= qt; kt++) {
        const int cb = kt * 128;
        const float* Kg = g_K + (size_t)h * SQ * DHEAD + (size_t)cb * DHEAD;
        float acc[2][8][4] = {};

        for (int k0 = 0; k0 < DHEAD; k0 += 32) {
            #pragma unroll
            for (int s = 0; s < 4; s++) {
                const int row = r + s * 32;
                cp16(kvb + (row * KPAD + c4) * 4, &Kg[(size_t)row * DHEAD + k0 + c4]);
            }
            cp_commit();
            cp_wait<0>();
            __syncthreads();
            #pragma unroll
            for (int kk = 0; kk < 32; kk += 8) {
                uint32_t af[2][4];
                #pragma unroll
                for (int mt = 0; mt < 2; mt++) {
                    const int m0 = m0b + mt * 16 + g;
                    const float2 q0 = *reinterpret_cast<const float2*>(
                        &Qs[m0 * QLD + k0 + kk + 2 * c]);
                    const float2 q1 = *reinterpret_cast<const float2*>(
                        &Qs[(m0 + 8) * QLD + k0 + kk + 2 * c]);
                    af[mt][0] = __float_as_uint(q0.x); af[mt][2] = __float_as_uint(q0.y);
                    af[mt][1] = __float_as_uint(q1.x); af[mt][3] = __float_as_uint(q1.y);
                }
                #pragma unroll
                for (int nt = 0; nt < 8; nt++) {
                    const float2 bb = *reinterpret_cast<const float2*>(
                        &KV[(wn * 64 + nt * 8 + g) * KPAD + kk + 2 * c]);
                    const uint32_t b0 = __float_as_uint(bb.x);
                    const uint32_t b1 = __float_as_uint(bb.y);
                    #pragma unroll
                    for (int mt = 0; mt < 2; mt++)
                        mma_tf32(acc[mt][nt], af[mt], b0, b1);
                }
            }
            __syncthreads();
        }

        float pmax[2][2] = {{-1e30f, -1e30f}, {-1e30f, -1e30f}};
        #pragma unroll
        for (int mt = 0; mt < 2; mt++)
            #pragma unroll
            for (int nt = 0; nt < 8; nt++)
                #pragma unroll
                for (int i = 0; i < 4; i++) {
                    float v = acc[mt][nt][i] * 0.08838834764831845f;
                    v = fast_tanh(v * 0.02f) * 50.0f;
                    if (kt == qt) {
                        const int rr = acc_row8(wm, mt, g, i);
                        const int cl = acc_col8(wn, nt, c, i);
                        if (cl > rr) v = -1e30f;
                    }
                    acc[mt][nt][i] = v;
                    pmax[mt][i >> 1] = fmaxf(pmax[mt][i >> 1], v);
                }
        #pragma unroll
        for (int mt = 0; mt < 2; mt++)
            #pragma unroll
            for (int rh = 0; rh < 2; rh++) {
                float p = pmax[mt][rh];
                p = fmaxf(p, __shfl_xor_sync(0xffffffffu, p, 1));
                p = fmaxf(p, __shfl_xor_sync(0xffffffffu, p, 2));
                pmax[mt][rh] = p;
            }
        if (c == 0) {
            #pragma unroll
            for (int mt = 0; mt < 2; mt++)
                #pragma unroll
                for (int rh = 0; rh < 2; rh++)
                    rmax[wn * 128 + m0b + mt * 16 + rh * 8 + g] = pmax[mt][rh];
        }
        __syncthreads();

        float mnew[2][2], scal[2][2], psum[2][2] = {};
        #pragma unroll
        for (int mt = 0; mt < 2; mt++)
            #pragma unroll
            for (int rh = 0; rh < 2; rh++) {
                const int rr = m0b + mt * 16 + rh * 8 + g;
                const float mo = m_state[rr];
                const float tm = fmaxf(rmax[rr], rmax[128 + rr]);
                const float mn = fmaxf(mo, tm);
                mnew[mt][rh] = mn;
                scal[mt][rh] = __expf(mo - mn);
            }
        #pragma unroll
        for (int mt = 0; mt < 2; mt++)
            #pragma unroll
            for (int nt = 0; nt < 8; nt++)
                #pragma unroll
                for (int i = 0; i < 4; i++) {
                    const int rr = acc_row8(wm, mt, g, i);
                    const int cl = acc_col8(wn, nt, c, i);
                    const float p = __expf(acc[mt][nt][i] - mnew[mt][i >> 1]);
                    psum[mt][i >> 1] += p;
                    Ps[rr * QLD + cl] = f2tf(p);
                }
        #pragma unroll
        for (int mt = 0; mt < 2; mt++)
            #pragma unroll
            for (int rh = 0; rh < 2; rh++) {
                float p = psum[mt][rh];
                p += __shfl_xor_sync(0xffffffffu, p, 1);
                p += __shfl_xor_sync(0xffffffffu, p, 2);
                psum[mt][rh] = p;
            }
        if (c == 0) {
            #pragma unroll
            for (int mt = 0; mt < 2; mt++)
                #pragma unroll
                for (int rh = 0; rh < 2; rh++)
                    rsum[wn * 128 + m0b + mt * 16 + rh * 8 + g] = psum[mt][rh];
        }
        __syncthreads();

        if (wn == 0 && c == 0) {
            #pragma unroll
            for (int mt = 0; mt < 2; mt++)
                #pragma unroll
                for (int rh = 0; rh < 2; rh++) {
                    const int rr = m0b + mt * 16 + rh * 8 + g;
                    l_state[rr] = l_state[rr] * scal[mt][rh] + rsum[rr] + rsum[128 + rr];
                    m_state[rr] = mnew[mt][rh];
                }
        }
        #pragma unroll
        for (int mt = 0; mt < 2; mt++)
            #pragma unroll
            for (int nt = 0; nt < 8; nt++)
                #pragma unroll
                for (int i = 0; i < 4; i++)
                    acc_o[mt][nt][i] *= scal[mt][i >> 1];

        const float* Vg = g_V + (size_t)h * SQ * DHEAD + (size_t)cb * DHEAD;
        for (int k0 = 0; k0 < 128; k0 += 32) {
            #pragma unroll
            for (int s = 0; s < 4; s++) {
                const int idx = s * 256 + tid;
                const int row = idx >> 5;
                const int cf  = (idx & 31) << 2;
                cp16(kvb + (row * VLD + cf) * 4, &Vg[(size_t)(k0 + row) * DHEAD + cf]);
            }
            cp_commit();
            cp_wait<0>();
            __syncthreads();
            #pragma unroll
            for (int kk = 0; kk < 32; kk += 8) {
                uint32_t af[2][4];
                #pragma unroll
                for (int mt = 0; mt < 2; mt++) {
                    const int m0 = m0b + mt * 16 + g;
                    const float2 p0 = *reinterpret_cast<const float2*>(
                        &Ps[m0 * QLD + k0 + kk + 2 * c]);
                    const float2 p1 = *reinterpret_cast<const float2*>(
                        &Ps[(m0 + 8) * QLD + k0 + kk + 2 * c]);
                    af[mt][0] = __float_as_uint(p0.x); af[mt][2] = __float_as_uint(p0.y);
                    af[mt][1] = __float_as_uint(p1.x); af[mt][3] = __float_as_uint(p1.y);
                }
                #pragma unroll
                for (int nt = 0; nt < 8; nt++) {
                    const int n0 = wn * 64 + nt * 8 + g;
                    const uint32_t b0 = __float_as_uint(KV[(kk + 2 * c) * VLD + n0]);
                    const uint32_t b1 = __float_as_uint(KV[(kk + 2 * c + 1) * VLD + n0]);
                    #pragma unroll
                    for (int mt = 0; mt < 2; mt++)
                        mma_tf32(acc_o[mt][nt], af[mt], b0, b1);
                }
            }
            __syncthreads();
        }
    }

    float inv[2][2];
    #pragma unroll
    for (int mt = 0; mt < 2; mt++)
        #pragma unroll
        for (int rh = 0; rh < 2; rh++)
            inv[mt][rh] = 1.0f / l_state[m0b + mt * 16 + rh * 8 + g];
    #pragma unroll
    for (int mt = 0; mt < 2; mt++)
        #pragma unroll
        for (int nt = 0; nt < 8; nt++)
            #pragma unroll
            for (int i = 0; i < 4; i++) {
                const int q  = rb + acc_row8(wm, mt, g, i);
                const int dh = acc_col8(wn, nt, c, i);
                g_attn[(size_t)q * DMODEL + h * DHEAD + dh] =
                    f2tf(acc_o[mt][nt][i] * inv[mt][i >> 1]);
            }
}

// ---------------- kernel 4: output projection -------------------------------
__global__ __launch_bounds__(256, 1) void oproj_kernel(float* __restrict__ out) {
    extern __shared__ float dsm[];
    const int rb = blockIdx.x * 256, cb = blockIdx.y * 128;
    float acc[4][8][4] = {};
    gemm256(g_attn + (size_t)rb * DMODEL, DMODEL,
            g_rwo + (size_t)cb * DMODEL, DMODEL, acc, dsm);

    const int tid = threadIdx.x, warp = tid >> 5, lane = tid & 31;
    const int wm = warp >> 1, wn = warp & 1, g = lane >> 2, c = lane & 3;
    #pragma unroll
    for (int mt = 0; mt < 4; mt++)
        #pragma unroll
        for (int nt = 0; nt < 8; nt++)
            #pragma unroll
            for (int i = 0; i < 4; i++) {
                const int s = rb + wm * 64 + mt * 16 + g + ((i >> 1) << 3);
                const int d = cb + wn * 64 + nt * 8 + c * 2 + (i & 1);
                out[(size_t)s * DMODEL + d] = acc[mt][nt][i];
            }
}

// ---------------- launch ----------------------------------------------------
extern "C" void kernel_launch(void* const* d_in, const int* in_sizes, int n_in,
                              void* d_out, int out_size) {
    (void)in_sizes; (void)n_in; (void)out_size;
    const float* x  = (const float*)d_in[0];
    const float* rc = (const float*)d_in[1];
    const float* rs = (const float*)d_in[2];
    const float* wq = (const float*)d_in[4];
    const float* wk = (const float*)d_in[5];
    const float* wv = (const float*)d_in[6];
    const float* wo = (const float*)d_in[7];
    float* out = (float*)d_out;

    float *d_rx, *d_rwq, *d_rwk, *d_rwv, *d_rwo;
    cudaGetSymbolAddress((void**)&d_rx,  g_rx);
    cudaGetSymbolAddress((void**)&d_rwq, g_rwq);
    cudaGetSymbolAddress((void**)&d_rwk, g_rwk);
    cudaGetSymbolAddress((void**)&d_rwv, g_rwv);
    cudaGetSymbolAddress((void**)&d_rwo, g_rwo);

    const int dense_smem = DSM_TOT * (int)sizeof(float);   // 120 KB
    const int flash_smem = FL_TOT * (int)sizeof(float);
    cudaFuncSetAttribute(flash_kernel,
                         cudaFuncAttributeMaxDynamicSharedMemorySize, flash_smem);
    cudaFuncSetAttribute(qkv_kernel,
                         cudaFuncAttributeMaxDynamicSharedMemorySize, dense_smem);
    cudaFuncSetAttribute(oproj_kernel,
                         cudaFuncAttributeMaxDynamicSharedMemorySize, dense_smem);

    const int prb = (SQ * DMODEL / 4) / 1024;   // 1024 blocks per 16MB array
    preround_kernel<<<prb, 256>>>(x,  d_rx);
    preround_kernel<<<prb, 256>>>(wq, d_rwq);
    preround_kernel<<<prb, 256>>>(wk, d_rwk);
    preround_kernel<<<prb, 256>>>(wv, d_rwv);
    preround_kernel<<<prb, 256>>>(wo, d_rwo);

    qkv_kernel<<<dim3(8, 16, 3), 256, dense_smem>>>();
    rope_kernel<<<16384, 256>>>(rc, rs);
    flash_kernel<<<256, 256, flash_smem>>>();
    oproj_kernel<<<dim3(8, 16), 256, dense_smem>>>(out);
}

// round 7
// speedup vs baseline: 1.4389x; 1.0255x over previous
#include <cuda_runtime.h>
#include <cstdint>
#include <cstddef>

#define SQ 2048
#define DMODEL 2048
#define NH 16
#define DHEAD 128
#define NCH (DMODEL / 32)

#define DPAD 40                  // smem tile stride (floats); 40%32==8 -> conflict-free float2
#define ATILE_F (256 * DPAD)     // A stage: 256 rows
#define BTILE_F (128 * DPAD)     // B stage: 128 rows
#define DSM_TOT (2 * ATILE_F + 2 * BTILE_F)   // 30720 floats = 120 KB
#define QLD 136
#define VLD 132
#define KPAD 40
#define KVTILE_F (128 * KPAD)

// ---------------- scratch (static device globals; no runtime allocation) ----
__device__ float g_Q[NH * SQ * DHEAD];
__device__ float g_K[NH * SQ * DHEAD];
__device__ float g_V[NH * SQ * DHEAD];
__device__ float g_attn[SQ * DMODEL];
__device__ float g_rx[SQ * DMODEL];
__device__ float g_rwq[SQ * DMODEL];
__device__ float g_rwk[SQ * DMODEL];
__device__ float g_rwv[SQ * DMODEL];
__device__ float g_rwo[SQ * DMODEL];

// ---------------- helpers ---------------------------------------------------
__device__ __forceinline__ float f2tf(float f) {
    uint32_t r;
    asm("cvt.rna.tf32.f32 %0, %1;" : "=r"(r) : "f"(f));
    return __uint_as_float(r);
}

__device__ __forceinline__ float fast_tanh(float x) {
    const float e = __expf(2.0f * x);
    return 1.0f - 2.0f / (e + 1.0f);
}

__device__ __forceinline__ uint32_t s2u(const void* p) {
    uint32_t a;
    asm("{ .reg .u64 t; cvta.to.shared.u64 t, %1; cvt.u32.u64 %0, t; }"
        : "=r"(a) : "l"(p));
    return a;
}

__device__ __forceinline__ void cp16(uint32_t s, const void* g) {
    asm volatile("cp.async.ca.shared.global [%0], [%1], 16;" :: "r"(s), "l"(g) : "memory");
}
__device__ __forceinline__ void cp_commit() {
    asm volatile("cp.async.commit_group;" ::: "memory");
}
template <int N>
__device__ __forceinline__ void cp_wait() {
    asm volatile("cp.async.wait_group %0;" :: "n"(N) : "memory");
}

__device__ __forceinline__ void mma_tf32(float acc[4], const uint32_t a[4],
                                         uint32_t b0, uint32_t b1) {
    asm volatile(
        "mma.sync.aligned.m16n8k8.row.col.f32.tf32.tf32.f32 "
        "{%0,%1,%2,%3}, {%4,%5,%6,%7}, {%8,%9}, {%0,%1,%2,%3};\n"
        : "+f"(acc[0]), "+f"(acc[1]), "+f"(acc[2]), "+f"(acc[3])
        : "r"(a[0]), "r"(a[1]), "r"(a[2]), "r"(a[3]), "r"(b0), "r"(b1));
}

__device__ __forceinline__ int acc_row8(int wm, int mt, int g, int i) {
    return wm * 32 + mt * 16 + g + ((i >> 1) << 3);
}
__device__ __forceinline__ int acc_col8(int wn, int nt, int c, int i) {
    return wn * 64 + nt * 8 + c * 2 + (i & 1);
}

// ---------------- kernel 0: pre-round fp32 -> tf32-exact fp32 ---------------
__global__ void preround_kernel(const float* __restrict__ src, float* __restrict__ dst) {
    const int base = blockIdx.x * 1024 + threadIdx.x;
    float4 v[4];
    #pragma unroll
    for (int k = 0; k < 4; k++)
        v[k] = reinterpret_cast<const float4*>(src)[base + k * 256];
    #pragma unroll
    for (int k = 0; k < 4; k++) {
        v[k].x = f2tf(v[k].x); v[k].y = f2tf(v[k].y);
        v[k].z = f2tf(v[k].z); v[k].w = f2tf(v[k].w);
        reinterpret_cast<float4*>(dst)[base + k * 256] = v[k];
    }
}

// ---------------- dense GEMM core: 256x128 CTA tile, warp tile 64x64 --------
// Fragment software pipelining: load kk+1 frags before issuing kk MMAs.
__device__ __forceinline__ void gemm256(const float* __restrict__ A, int lda,
                                        const float* __restrict__ B, int ldb,
                                        float acc[4][8][4], float* sm) {
    const int tid = threadIdx.x, warp = tid >> 5, lane = tid & 31;
    const int wm = warp >> 1, wn = warp & 1, g = lane >> 2, c = lane & 3;
    const int r = tid >> 3, c4 = (tid & 7) << 2;
    const uint32_t sb = s2u(sm);

    auto stage = [&](int buf, int k0) {
        const uint32_t abase = sb + (buf ? ATILE_F : 0) * 4;
        const uint32_t bbase = sb + (2 * ATILE_F + (buf ? BTILE_F : 0)) * 4;
        #pragma unroll
        for (int s = 0; s < 8; s++) {
            const int row = r + s * 32;
            cp16(abase + (row * DPAD + c4) * 4, &A[(size_t)row * lda + k0 + c4]);
        }
        #pragma unroll
        for (int s = 0; s < 4; s++) {
            const int row = r + s * 32;
            cp16(bbase + (row * DPAD + c4) * 4, &B[(size_t)row * ldb + k0 + c4]);
        }
    };

    stage(0, 0);
    cp_commit();

    for (int ch = 0; ch < NCH; ch++) {
        const int buf = ch & 1;
        if (ch + 1 < NCH) {
            stage(buf ^ 1, (ch + 1) * 32);
            cp_commit();
            cp_wait<1>();
        } else {
            cp_wait<0>();
        }
        __syncthreads();

        const float* Ab = sm + (buf ? ATILE_F : 0);
        const float* Bb = sm + 2 * ATILE_F + (buf ? BTILE_F : 0);

        uint32_t afb[2][4][4];
        uint32_t bfb[2][8][2];

        auto ldfrag = [&](int kk, int fb) {
            #pragma unroll
            for (int mt = 0; mt < 4; mt++) {
                const int m0 = wm * 64 + mt * 16 + g;
                const float2 p0 = *reinterpret_cast<const float2*>(&Ab[m0 * DPAD + kk + 2 * c]);
                const float2 p1 = *reinterpret_cast<const float2*>(&Ab[(m0 + 8) * DPAD + kk + 2 * c]);
                afb[fb][mt][0] = __float_as_uint(p0.x); afb[fb][mt][2] = __float_as_uint(p0.y);
                afb[fb][mt][1] = __float_as_uint(p1.x); afb[fb][mt][3] = __float_as_uint(p1.y);
            }
            #pragma unroll
            for (int nt = 0; nt < 8; nt++) {
                const float2 bb = *reinterpret_cast<const float2*>(
                    &Bb[(wn * 64 + nt * 8 + g) * DPAD + kk + 2 * c]);
                bfb[fb][nt][0] = __float_as_uint(bb.x);
                bfb[fb][nt][1] = __float_as_uint(bb.y);
            }
        };

        ldfrag(0, 0);
        #pragma unroll
        for (int ks = 0; ks < 4; ks++) {
            const int cur = ks & 1;
            if (ks < 3) ldfrag((ks + 1) * 8, cur ^ 1);
            #pragma unroll
            for (int nt = 0; nt < 8; nt++)
                #pragma unroll
                for (int mt = 0; mt < 4; mt++)
                    mma_tf32(acc[mt][nt], afb[cur][mt], bfb[cur][nt][0], bfb[cur][nt][1]);
        }
        __syncthreads();
    }
}

// ---------------- kernel 1: QKV projections --------------------------------
__global__ __launch_bounds__(256, 1) void qkv_kernel() {
    extern __shared__ float dsm[];
    const int which = blockIdx.z;
    const float* W = (which == 0) ? g_rwq : (which == 1) ? g_rwk : g_rwv;
    float* out = (which == 0) ? g_Q : (which == 1) ? g_K : g_V;

    const int rb = blockIdx.x * 256;
    const int cb = blockIdx.y * 128;
    float acc[4][8][4] = {};
    gemm256(g_rx + (size_t)rb * DMODEL, DMODEL,
            W + (size_t)cb * DMODEL, DMODEL, acc, dsm);

    const int tid = threadIdx.x, warp = tid >> 5, lane = tid & 31;
    const int wm = warp >> 1, wn = warp & 1, g = lane >> 2, c = lane & 3;
    const bool roundV = (which == 2);
    #pragma unroll
    for (int mt = 0; mt < 4; mt++)
        #pragma unroll
        for (int nt = 0; nt < 8; nt++)
            #pragma unroll
            for (int i = 0; i < 4; i++) {
                const int s = rb + wm * 64 + mt * 16 + g + ((i >> 1) << 3);
                const int p = cb + wn * 64 + nt * 8 + c * 2 + (i & 1);
                const int h = p >> 7, dh = p & 127;
                const float v = roundV ? f2tf(acc[mt][nt][i]) : acc[mt][nt][i];
                out[(size_t)h * SQ * DHEAD + (size_t)s * DHEAD + dh] = v;
            }
}

// ---------------- kernel 2: RoPE in-place, stores tf32-exact ----------------
__global__ void rope_kernel(const float* __restrict__ cosb,
                            const float* __restrict__ sinb) {
    const int t = blockIdx.x * blockDim.x + threadIdx.x;
    const int d  = t & 63;
    const int s  = (t >> 6) & (SQ - 1);
    const int h  = (t >> 17) & (NH - 1);
    const int qk = t >> 21;
    float* p = (qk ? g_K : g_Q) + (size_t)h * SQ * DHEAD + (size_t)s * DHEAD;
    const float x0 = p[d], x1 = p[d + 64];
    const float c0 = cosb[s * DHEAD + d],      s0 = sinb[s * DHEAD + d];
    const float c1 = cosb[s * DHEAD + d + 64], s1 = sinb[s * DHEAD + d + 64];
    p[d]      = f2tf(x0 * c0 - x1 * s0);
    p[d + 64] = f2tf(x1 * c1 + x0 * s1);
}

// ---------------- kernel 3: flash attention ---------------------------------
#define FL_QS 0
#define FL_PS (128 * QLD)
#define FL_KV (2 * 128 * QLD)
#define FL_M  (FL_KV + KVTILE_F)
#define FL_L  (FL_M + 128)
#define FL_RMAX (FL_L + 128)
#define FL_RSUM (FL_RMAX + 256)
#define FL_TOT  (FL_RSUM + 256)

__global__ __launch_bounds__(256) void flash_kernel() {
    extern __shared__ float sm[];
    float* Qs = sm + FL_QS;
    float* Ps = sm + FL_PS;
    float* KV = sm + FL_KV;
    float* m_state = sm + FL_M;
    float* l_state = sm + FL_L;
    float* rmax = sm + FL_RMAX;
    float* rsum = sm + FL_RSUM;
    const uint32_t kvb = s2u(KV);

    const int bid = blockIdx.x;
    const int qt  = 15 - (bid >> 4);
    const int h   = bid & 15;
    const int rb  = qt * 128;

    const int tid = threadIdx.x, warp = tid >> 5, lane = tid & 31;
    const int wm = warp >> 1, wn = warp & 1, g = lane >> 2, c = lane & 3;
    const int m0b = wm * 32;
    const int r = tid >> 3, c4 = (tid & 7) << 2;

    if (tid < 128) { m_state[tid] = -1e30f; l_state[tid] = 0.f; }

    {
        const float* Qg = g_Q + (size_t)h * SQ * DHEAD + (size_t)rb * DHEAD;
        #pragma unroll
        for (int s = 0; s < 4; s++)
            #pragma unroll
            for (int cc = 0; cc < 4; cc++) {
                const int row = r + s * 32, col = c4 + cc * 32;
                *reinterpret_cast<float4*>(&Qs[row * QLD + col]) =
                    *reinterpret_cast<const float4*>(&Qg[(size_t)row * DHEAD + col]);
            }
    }
    __syncthreads();

    float acc_o[2][8][4] = {};

    for (int kt = 0; kt <= qt; kt++) {
        const int cb = kt * 128;
        const float* Kg = g_K + (size_t)h * SQ * DHEAD + (size_t)cb * DHEAD;
        float acc[2][8][4] = {};

        for (int k0 = 0; k0 < DHEAD; k0 += 32) {
            #pragma unroll
            for (int s = 0; s < 4; s++) {
                const int row = r + s * 32;
                cp16(kvb + (row * KPAD + c4) * 4, &Kg[(size_t)row * DHEAD + k0 + c4]);
            }
            cp_commit();
            cp_wait<0>();
            __syncthreads();
            #pragma unroll
            for (int kk = 0; kk < 32; kk += 8) {
                uint32_t af[2][4];
                #pragma unroll
                for (int mt = 0; mt < 2; mt++) {
                    const int m0 = m0b + mt * 16 + g;
                    const float2 q0 = *reinterpret_cast<const float2*>(
                        &Qs[m0 * QLD + k0 + kk + 2 * c]);
                    const float2 q1 = *reinterpret_cast<const float2*>(
                        &Qs[(m0 + 8) * QLD + k0 + kk + 2 * c]);
                    af[mt][0] = __float_as_uint(q0.x); af[mt][2] = __float_as_uint(q0.y);
                    af[mt][1] = __float_as_uint(q1.x); af[mt][3] = __float_as_uint(q1.y);
                }
                #pragma unroll
                for (int nt = 0; nt < 8; nt++) {
                    const float2 bb = *reinterpret_cast<const float2*>(
                        &KV[(wn * 64 + nt * 8 + g) * KPAD + kk + 2 * c]);
                    const uint32_t b0 = __float_as_uint(bb.x);
                    const uint32_t b1 = __float_as_uint(bb.y);
                    #pragma unroll
                    for (int mt = 0; mt < 2; mt++)
                        mma_tf32(acc[mt][nt], af[mt], b0, b1);
                }
            }
            __syncthreads();
        }

        float pmax[2][2] = {{-1e30f, -1e30f}, {-1e30f, -1e30f}};
        #pragma unroll
        for (int mt = 0; mt < 2; mt++)
            #pragma unroll
            for (int nt = 0; nt < 8; nt++)
                #pragma unroll
                for (int i = 0; i < 4; i++) {
                    float v = acc[mt][nt][i] * 0.08838834764831845f;
                    v = fast_tanh(v * 0.02f) * 50.0f;
                    if (kt == qt) {
                        const int rr = acc_row8(wm, mt, g, i);
                        const int cl = acc_col8(wn, nt, c, i);
                        if (cl > rr) v = -1e30f;
                    }
                    acc[mt][nt][i] = v;
                    pmax[mt][i >> 1] = fmaxf(pmax[mt][i >> 1], v);
                }
        #pragma unroll
        for (int mt = 0; mt < 2; mt++)
            #pragma unroll
            for (int rh = 0; rh < 2; rh++) {
                float p = pmax[mt][rh];
                p = fmaxf(p, __shfl_xor_sync(0xffffffffu, p, 1));
                p = fmaxf(p, __shfl_xor_sync(0xffffffffu, p, 2));
                pmax[mt][rh] = p;
            }
        if (c == 0) {
            #pragma unroll
            for (int mt = 0; mt < 2; mt++)
                #pragma unroll
                for (int rh = 0; rh < 2; rh++)
                    rmax[wn * 128 + m0b + mt * 16 + rh * 8 + g] = pmax[mt][rh];
        }
        __syncthreads();

        float mnew[2][2], scal[2][2], psum[2][2] = {};
        #pragma unroll
        for (int mt = 0; mt < 2; mt++)
            #pragma unroll
            for (int rh = 0; rh < 2; rh++) {
                const int rr = m0b + mt * 16 + rh * 8 + g;
                const float mo = m_state[rr];
                const float tm = fmaxf(rmax[rr], rmax[128 + rr]);
                const float mn = fmaxf(mo, tm);
                mnew[mt][rh] = mn;
                scal[mt][rh] = __expf(mo - mn);
            }
        #pragma unroll
        for (int mt = 0; mt < 2; mt++)
            #pragma unroll
            for (int nt = 0; nt < 8; nt++)
                #pragma unroll
                for (int i = 0; i < 4; i++) {
                    const int rr = acc_row8(wm, mt, g, i);
                    const int cl = acc_col8(wn, nt, c, i);
                    const float p = __expf(acc[mt][nt][i] - mnew[mt][i >> 1]);
                    psum[mt][i >> 1] += p;
                    Ps[rr * QLD + cl] = f2tf(p);
                }
        #pragma unroll
        for (int mt = 0; mt < 2; mt++)
            #pragma unroll
            for (int rh = 0; rh < 2; rh++) {
                float p = psum[mt][rh];
                p += __shfl_xor_sync(0xffffffffu, p, 1);
                p += __shfl_xor_sync(0xffffffffu, p, 2);
                psum[mt][rh] = p;
            }
        if (c == 0) {
            #pragma unroll
            for (int mt = 0; mt < 2; mt++)
                #pragma unroll
                for (int rh = 0; rh < 2; rh++)
                    rsum[wn * 128 + m0b + mt * 16 + rh * 8 + g] = psum[mt][rh];
        }
        __syncthreads();

        if (wn == 0 && c == 0) {
            #pragma unroll
            for (int mt = 0; mt < 2; mt++)
                #pragma unroll
                for (int rh = 0; rh < 2; rh++) {
                    const int rr = m0b + mt * 16 + rh * 8 + g;
                    l_state[rr] = l_state[rr] * scal[mt][rh] + rsum[rr] + rsum[128 + rr];
                    m_state[rr] = mnew[mt][rh];
                }
        }
        #pragma unroll
        for (int mt = 0; mt < 2; mt++)
            #pragma unroll
            for (int nt = 0; nt < 8; nt++)
                #pragma unroll
                for (int i = 0; i < 4; i++)
                    acc_o[mt][nt][i] *= scal[mt][i >> 1];

        const float* Vg = g_V + (size_t)h * SQ * DHEAD + (size_t)cb * DHEAD;
        for (int k0 = 0; k0 < 128; k0 += 32) {
            #pragma unroll
            for (int s = 0; s < 4; s++) {
                const int idx = s * 256 + tid;
                const int row = idx >> 5;
                const int cf  = (idx & 31) << 2;
                cp16(kvb + (row * VLD + cf) * 4, &Vg[(size_t)(k0 + row) * DHEAD + cf]);
            }
            cp_commit();
            cp_wait<0>();
            __syncthreads();
            #pragma unroll
            for (int kk = 0; kk < 32; kk += 8) {
                uint32_t af[2][4];
                #pragma unroll
                for (int mt = 0; mt < 2; mt++) {
                    const int m0 = m0b + mt * 16 + g;
                    const float2 p0 = *reinterpret_cast<const float2*>(
                        &Ps[m0 * QLD + k0 + kk + 2 * c]);
                    const float2 p1 = *reinterpret_cast<const float2*>(
                        &Ps[(m0 + 8) * QLD + k0 + kk + 2 * c]);
                    af[mt][0] = __float_as_uint(p0.x); af[mt][2] = __float_as_uint(p0.y);
                    af[mt][1] = __float_as_uint(p1.x); af[mt][3] = __float_as_uint(p1.y);
                }
                #pragma unroll
                for (int nt = 0; nt < 8; nt++) {
                    const int n0 = wn * 64 + nt * 8 + g;
                    const uint32_t b0 = __float_as_uint(KV[(kk + 2 * c) * VLD + n0]);
                    const uint32_t b1 = __float_as_uint(KV[(kk + 2 * c + 1) * VLD + n0]);
                    #pragma unroll
                    for (int mt = 0; mt < 2; mt++)
                        mma_tf32(acc_o[mt][nt], af[mt], b0, b1);
                }
            }
            __syncthreads();
        }
    }

    float inv[2][2];
    #pragma unroll
    for (int mt = 0; mt < 2; mt++)
        #pragma unroll
        for (int rh = 0; rh < 2; rh++)
            inv[mt][rh] = 1.0f / l_state[m0b + mt * 16 + rh * 8 + g];
    #pragma unroll
    for (int mt = 0; mt < 2; mt++)
        #pragma unroll
        for (int nt = 0; nt < 8; nt++)
            #pragma unroll
            for (int i = 0; i < 4; i++) {
                const int q  = rb + acc_row8(wm, mt, g, i);
                const int dh = acc_col8(wn, nt, c, i);
                g_attn[(size_t)q * DMODEL + h * DHEAD + dh] =
                    f2tf(acc_o[mt][nt][i] * inv[mt][i >> 1]);
            }
}

// ---------------- kernel 4: output projection -------------------------------
__global__ __launch_bounds__(256, 1) void oproj_kernel(float* __restrict__ out) {
    extern __shared__ float dsm[];
    const int rb = blockIdx.x * 256, cb = blockIdx.y * 128;
    float acc[4][8][4] = {};
    gemm256(g_attn + (size_t)rb * DMODEL, DMODEL,
            g_rwo + (size_t)cb * DMODEL, DMODEL, acc, dsm);

    const int tid = threadIdx.x, warp = tid >> 5, lane = tid & 31;
    const int wm = warp >> 1, wn = warp & 1, g = lane >> 2, c = lane & 3;
    #pragma unroll
    for (int mt = 0; mt < 4; mt++)
        #pragma unroll
        for (int nt = 0; nt < 8; nt++)
            #pragma unroll
            for (int i = 0; i < 4; i++) {
                const int s = rb + wm * 64 + mt * 16 + g + ((i >> 1) << 3);
                const int d = cb + wn * 64 + nt * 8 + c * 2 + (i & 1);
                out[(size_t)s * DMODEL + d] = acc[mt][nt][i];
            }
}

// ---------------- launch ----------------------------------------------------
extern "C" void kernel_launch(void* const* d_in, const int* in_sizes, int n_in,
                              void* d_out, int out_size) {
    (void)in_sizes; (void)n_in; (void)out_size;
    const float* x  = (const float*)d_in[0];
    const float* rc = (const float*)d_in[1];
    const float* rs = (const float*)d_in[2];
    const float* wq = (const float*)d_in[4];
    const float* wk = (const float*)d_in[5];
    const float* wv = (const float*)d_in[6];
    const float* wo = (const float*)d_in[7];
    float* out = (float*)d_out;

    float *d_rx, *d_rwq, *d_rwk, *d_rwv, *d_rwo;
    cudaGetSymbolAddress((void**)&d_rx,  g_rx);
    cudaGetSymbolAddress((void**)&d_rwq, g_rwq);
    cudaGetSymbolAddress((void**)&d_rwk, g_rwk);
    cudaGetSymbolAddress((void**)&d_rwv, g_rwv);
    cudaGetSymbolAddress((void**)&d_rwo, g_rwo);

    const int dense_smem = DSM_TOT * (int)sizeof(float);   // 120 KB
    const int flash_smem = FL_TOT * (int)sizeof(float);
    cudaFuncSetAttribute(flash_kernel,
                         cudaFuncAttributeMaxDynamicSharedMemorySize, flash_smem);
    cudaFuncSetAttribute(qkv_kernel,
                         cudaFuncAttributeMaxDynamicSharedMemorySize, dense_smem);
    cudaFuncSetAttribute(oproj_kernel,
                         cudaFuncAttributeMaxDynamicSharedMemorySize, dense_smem);

    const int prb = (SQ * DMODEL / 4) / 1024;
    preround_kernel<<<prb, 256>>>(x,  d_rx);
    preround_kernel<<<prb, 256>>>(wq, d_rwq);
    preround_kernel<<<prb, 256>>>(wk, d_rwk);
    preround_kernel<<<prb, 256>>>(wv, d_rwv);
    preround_kernel<<<prb, 256>>>(wo, d_rwo);

    qkv_kernel<<<dim3(8, 16, 3), 256, dense_smem>>>();
    rope_kernel<<<16384, 256>>>(rc, rs);
    flash_kernel<<<256, 256, flash_smem>>>();
    oproj_kernel<<<dim3(8, 16), 256, dense_smem>>>(out);
}

// round 10
// speedup vs baseline: 1.4620x; 1.0160x over previous
#include <cuda_runtime.h>
#include <cstdint>
#include <cstddef>

#define SQ 2048
#define DMODEL 2048
#define NH 16
#define DHEAD 128
#define NCH (DMODEL / 32)

#define DPAD 40                  // dense smem stride; 40%32==8 -> conflict-free float2
#define ATILE_F (256 * DPAD)
#define BTILE_F (128 * DPAD)
#define DSM_TOT (2 * ATILE_F + 2 * BTILE_F)   // 120 KB
#define QLD 136                  // flash Q/P stride (%32==8, float2 frags)
#define KLD 136                  // flash K-phase stride (%32==8)
#define VLD 132                  // flash V-phase stride (%32==4, scalar frags)

// ---------------- scratch ----------------------------------------------------
__device__ float g_Q[NH * SQ * DHEAD];
__device__ float g_K[NH * SQ * DHEAD];
__device__ float g_V[NH * SQ * DHEAD];
__device__ float g_attn[SQ * DMODEL];

// ---------------- helpers ---------------------------------------------------
__device__ __forceinline__ float f2tf(float f) {
    uint32_t r;
    asm("cvt.rna.tf32.f32 %0, %1;" : "=r"(r) : "f"(f));
    return __uint_as_float(r);
}
__device__ __forceinline__ uint32_t f2tfu(float f) {
    uint32_t r;
    asm("cvt.rna.tf32.f32 %0, %1;" : "=r"(r) : "f"(f));
    return r;
}

__device__ __forceinline__ float fast_tanh(float x) {
    const float e = __expf(2.0f * x);
    return 1.0f - 2.0f / (e + 1.0f);
}

__device__ __forceinline__ uint32_t s2u(const void* p) {
    uint32_t a;
    asm("{ .reg .u64 t; cvta.to.shared.u64 t, %1; cvt.u32.u64 %0, t; }"
        : "=r"(a) : "l"(p));
    return a;
}

__device__ __forceinline__ void cp16(uint32_t s, const void* g) {
    asm volatile("cp.async.ca.shared.global [%0], [%1], 16;" :: "r"(s), "l"(g) : "memory");
}
__device__ __forceinline__ void cp_commit() {
    asm volatile("cp.async.commit_group;" ::: "memory");
}
template <int N>
__device__ __forceinline__ void cp_wait() {
    asm volatile("cp.async.wait_group %0;" :: "n"(N) : "memory");
}

__device__ __forceinline__ void mma_tf32(float acc[4], const uint32_t a[4],
                                         uint32_t b0, uint32_t b1) {
    asm volatile(
        "mma.sync.aligned.m16n8k8.row.col.f32.tf32.tf32.f32 "
        "{%0,%1,%2,%3}, {%4,%5,%6,%7}, {%8,%9}, {%0,%1,%2,%3};\n"
        : "+f"(acc[0]), "+f"(acc[1]), "+f"(acc[2]), "+f"(acc[3])
        : "r"(a[0]), "r"(a[1]), "r"(a[2]), "r"(a[3]), "r"(b0), "r"(b1));
}

__device__ __forceinline__ int acc_row8(int wm, int mt, int g, int i) {
    return wm * 32 + mt * 16 + g + ((i >> 1) << 3);
}
__device__ __forceinline__ int acc_col8(int wn, int nt, int c, int i) {
    return wn * 64 + nt * 8 + c * 2 + (i & 1);
}

// ---------------- dense GEMM core: 256x128 CTA, warp 64x64, cvt-in-frag -----
__device__ __forceinline__ void gemm256(const float* __restrict__ A, int lda,
                                        const float* __restrict__ B, int ldb,
                                        float acc[4][8][4], float* sm) {
    const int tid = threadIdx.x, warp = tid >> 5, lane = tid & 31;
    const int wm = warp >> 1, wn = warp & 1, g = lane >> 2, c = lane & 3;
    const int r = tid >> 3, c4 = (tid & 7) << 2;
    const uint32_t sb = s2u(sm);

    auto stage = [&](int buf, int k0) {
        const uint32_t abase = sb + (buf ? ATILE_F : 0) * 4;
        const uint32_t bbase = sb + (2 * ATILE_F + (buf ? BTILE_F : 0)) * 4;
        #pragma unroll
        for (int s = 0; s < 8; s++) {
            const int row = r + s * 32;
            cp16(abase + (row * DPAD + c4) * 4, &A[(size_t)row * lda + k0 + c4]);
        }
        #pragma unroll
        for (int s = 0; s < 4; s++) {
            const int row = r + s * 32;
            cp16(bbase + (row * DPAD + c4) * 4, &B[(size_t)row * ldb + k0 + c4]);
        }
    };

    stage(0, 0);
    cp_commit();

    for (int ch = 0; ch < NCH; ch++) {
        const int buf = ch & 1;
        if (ch + 1 < NCH) {
            stage(buf ^ 1, (ch + 1) * 32);
            cp_commit();
            cp_wait<1>();
        } else {
            cp_wait<0>();
        }
        __syncthreads();

        const float* Ab = sm + (buf ? ATILE_F : 0);
        const float* Bb = sm + 2 * ATILE_F + (buf ? BTILE_F : 0);

        uint32_t afb[2][4][4];
        uint32_t bfb[2][8][2];

        auto ldfrag = [&](int kk, int fb) {
            #pragma unroll
            for (int mt = 0; mt < 4; mt++) {
                const int m0 = wm * 64 + mt * 16 + g;
                const float2 p0 = *reinterpret_cast<const float2*>(&Ab[m0 * DPAD + kk + 2 * c]);
                const float2 p1 = *reinterpret_cast<const float2*>(&Ab[(m0 + 8) * DPAD + kk + 2 * c]);
                afb[fb][mt][0] = f2tfu(p0.x); afb[fb][mt][2] = f2tfu(p0.y);
                afb[fb][mt][1] = f2tfu(p1.x); afb[fb][mt][3] = f2tfu(p1.y);
            }
            #pragma unroll
            for (int nt = 0; nt < 8; nt++) {
                const float2 bb = *reinterpret_cast<const float2*>(
                    &Bb[(wn * 64 + nt * 8 + g) * DPAD + kk + 2 * c]);
                bfb[fb][nt][0] = f2tfu(bb.x);
                bfb[fb][nt][1] = f2tfu(bb.y);
            }
        };

        ldfrag(0, 0);
        #pragma unroll
        for (int ks = 0; ks < 4; ks++) {
            const int cur = ks & 1;
            if (ks < 3) ldfrag((ks + 1) * 8, cur ^ 1);
            #pragma unroll
            for (int nt = 0; nt < 8; nt++)
                #pragma unroll
                for (int mt = 0; mt < 4; mt++)
                    mma_tf32(acc[mt][nt], afb[cur][mt], bfb[cur][nt][0], bfb[cur][nt][1]);
        }
        __syncthreads();
    }
}

// ---------------- kernel 1: QKV projections --------------------------------
__global__ __launch_bounds__(256, 1) void qkv_kernel(const float* __restrict__ x,
                                                     const float* __restrict__ wq,
                                                     const float* __restrict__ wk,
                                                     const float* __restrict__ wv) {
    extern __shared__ float dsm[];
    const int which = blockIdx.z;
    const float* W = (which == 0) ? wq : (which == 1) ? wk : wv;
    float* out = (which == 0) ? g_Q : (which == 1) ? g_K : g_V;

    const int rb = blockIdx.x * 256;
    const int cb = blockIdx.y * 128;
    float acc[4][8][4] = {};
    gemm256(x + (size_t)rb * DMODEL, DMODEL,
            W + (size_t)cb * DMODEL, DMODEL, acc, dsm);

    const int tid = threadIdx.x, warp = tid >> 5, lane = tid & 31;
    const int wm = warp >> 1, wn = warp & 1, g = lane >> 2, c = lane & 3;
    const bool roundV = (which == 2);
    #pragma unroll
    for (int mt = 0; mt < 4; mt++)
        #pragma unroll
        for (int nt = 0; nt < 8; nt++)
            #pragma unroll
            for (int i = 0; i < 4; i++) {
                const int s = rb + wm * 64 + mt * 16 + g + ((i >> 1) << 3);
                const int p = cb + wn * 64 + nt * 8 + c * 2 + (i & 1);
                const int h = p >> 7, dh = p & 127;
                const float v = roundV ? f2tf(acc[mt][nt][i]) : acc[mt][nt][i];
                out[(size_t)h * SQ * DHEAD + (size_t)s * DHEAD + dh] = v;
            }
}

// ---------------- kernel 2: RoPE in-place, stores tf32-exact ----------------
__global__ void rope_kernel(const float* __restrict__ cosb,
                            const float* __restrict__ sinb) {
    const int t = blockIdx.x * blockDim.x + threadIdx.x;
    const int d  = t & 63;
    const int s  = (t >> 6) & (SQ - 1);
    const int h  = (t >> 17) & (NH - 1);
    const int qk = t >> 21;
    float* p = (qk ? g_K : g_Q) + (size_t)h * SQ * DHEAD + (size_t)s * DHEAD;
    const float x0 = p[d], x1 = p[d + 64];
    const float c0 = cosb[s * DHEAD + d],      s0 = sinb[s * DHEAD + d];
    const float c1 = cosb[s * DHEAD + d + 64], s1 = sinb[s * DHEAD + d + 64];
    p[d]      = f2tf(x0 * c0 - x1 * s0);
    p[d + 64] = f2tf(x1 * c1 + x0 * s1);
}

// ---------------- kernel 3: flash attention, full-tile K/V staging ----------
#define FL_QS 0
#define FL_PS (128 * QLD)
#define FL_KV (2 * 128 * QLD)
#define FL_M  (FL_KV + 128 * KLD)
#define FL_L  (FL_M + 128)
#define FL_RMAX (FL_L + 128)
#define FL_RSUM (FL_RMAX + 256)
#define FL_TOT  (FL_RSUM + 256)

__global__ __launch_bounds__(256) void flash_kernel() {
    extern __shared__ float sm[];
    float* Qs = sm + FL_QS;
    float* Ps = sm + FL_PS;
    float* KV = sm + FL_KV;
    float* m_state = sm + FL_M;
    float* l_state = sm + FL_L;
    float* rmax = sm + FL_RMAX;
    float* rsum = sm + FL_RSUM;
    const uint32_t kvb = s2u(KV);

    const int bid = blockIdx.x;
    const int qt  = 15 - (bid >> 4);
    const int h   = bid & 15;
    const int rb  = qt * 128;

    const int tid = threadIdx.x, warp = tid >> 5, lane = tid & 31;
    const int wm = warp >> 1, wn = warp & 1, g = lane >> 2, c = lane & 3;
    const int m0b = wm * 32;
    const int r = tid >> 3, c4 = (tid & 7) << 2;

    if (tid < 128) { m_state[tid] = -1e30f; l_state[tid] = 0.f; }

    // Q tile (tf32-exact): direct copy
    {
        const float* Qg = g_Q + (size_t)h * SQ * DHEAD + (size_t)rb * DHEAD;
        #pragma unroll
        for (int s = 0; s < 4; s++)
            #pragma unroll
            for (int cc = 0; cc < 4; cc++) {
                const int row = r + s * 32, col = c4 + cc * 32;
                *reinterpret_cast<float4*>(&Qs[row * QLD + col]) =
                    *reinterpret_cast<const float4*>(&Qg[(size_t)row * DHEAD + col]);
            }
    }

    float acc_o[2][8][4] = {};

    for (int kt = 0; kt <= qt; kt++) {
        const int cb = kt * 128;
        const float* Kg = g_K + (size_t)h * SQ * DHEAD + (size_t)cb * DHEAD;
        const float* Vg = g_V + (size_t)h * SQ * DHEAD + (size_t)cb * DHEAD;
        float acc[2][8][4] = {};

        // ---- stage FULL K tile (128x128) stride KLD ----
        __syncthreads();   // prior PV reads of KV done; Q copy visible (kt==0)
        #pragma unroll
        for (int s = 0; s < 16; s++) {
            const int idx = s * 256 + tid;
            const int row = idx >> 5;
            const int cf  = (idx & 31) << 2;
            cp16(kvb + (row * KLD + cf) * 4, &Kg[(size_t)row * DHEAD + cf]);
        }
        cp_commit();
        cp_wait<0>();
        __syncthreads();

        // ---- S = Q @ K^T : 16 uninterrupted kk steps ----
        #pragma unroll
        for (int kk = 0; kk < 128; kk += 8) {
            uint32_t af[2][4];
            #pragma unroll
            for (int mt = 0; mt < 2; mt++) {
                const int m0 = m0b + mt * 16 + g;
                const float2 q0 = *reinterpret_cast<const float2*>(&Qs[m0 * QLD + kk + 2 * c]);
                const float2 q1 = *reinterpret_cast<const float2*>(&Qs[(m0 + 8) * QLD + kk + 2 * c]);
                af[mt][0] = __float_as_uint(q0.x); af[mt][2] = __float_as_uint(q0.y);
                af[mt][1] = __float_as_uint(q1.x); af[mt][3] = __float_as_uint(q1.y);
            }
            #pragma unroll
            for (int nt = 0; nt < 8; nt++) {
                const float2 bb = *reinterpret_cast<const float2*>(
                    &KV[(wn * 64 + nt * 8 + g) * KLD + kk + 2 * c]);
                const uint32_t b0 = __float_as_uint(bb.x);
                const uint32_t b1 = __float_as_uint(bb.y);
                #pragma unroll
                for (int mt = 0; mt < 2; mt++)
                    mma_tf32(acc[mt][nt], af[mt], b0, b1);
            }
        }

        // ---- softcap + mask + row max ----
        float pmax[2][2] = {{-1e30f, -1e30f}, {-1e30f, -1e30f}};
        #pragma unroll
        for (int mt = 0; mt < 2; mt++)
            #pragma unroll
            for (int nt = 0; nt < 8; nt++)
                #pragma unroll
                for (int i = 0; i < 4; i++) {
                    float v = acc[mt][nt][i] * 0.08838834764831845f;
                    v = fast_tanh(v * 0.02f) * 50.0f;
                    if (kt == qt) {
                        const int rr = acc_row8(wm, mt, g, i);
                        const int cl = acc_col8(wn, nt, c, i);
                        if (cl > rr) v = -1e30f;
                    }
                    acc[mt][nt][i] = v;
                    pmax[mt][i >> 1] = fmaxf(pmax[mt][i >> 1], v);
                }
        #pragma unroll
        for (int mt = 0; mt < 2; mt++)
            #pragma unroll
            for (int rh = 0; rh < 2; rh++) {
                float p = pmax[mt][rh];
                p = fmaxf(p, __shfl_xor_sync(0xffffffffu, p, 1));
                p = fmaxf(p, __shfl_xor_sync(0xffffffffu, p, 2));
                pmax[mt][rh] = p;
            }
        if (c == 0) {
            #pragma unroll
            for (int mt = 0; mt < 2; mt++)
                #pragma unroll
                for (int rh = 0; rh < 2; rh++)
                    rmax[wn * 128 + m0b + mt * 16 + rh * 8 + g] = pmax[mt][rh];
        }
        __syncthreads();

        float mnew[2][2], scal[2][2], psum[2][2] = {};
        #pragma unroll
        for (int mt = 0; mt < 2; mt++)
            #pragma unroll
            for (int rh = 0; rh < 2; rh++) {
                const int rr = m0b + mt * 16 + rh * 8 + g;
                const float mo = m_state[rr];
                const float tm = fmaxf(rmax[rr], rmax[128 + rr]);
                const float mn = fmaxf(mo, tm);
                mnew[mt][rh] = mn;
                scal[mt][rh] = __expf(mo - mn);
            }
        #pragma unroll
        for (int mt = 0; mt < 2; mt++)
            #pragma unroll
            for (int nt = 0; nt < 8; nt++)
                #pragma unroll
                for (int i = 0; i < 4; i++) {
                    const int rr = acc_row8(wm, mt, g, i);
                    const int cl = acc_col8(wn, nt, c, i);
                    const float p = __expf(acc[mt][nt][i] - mnew[mt][i >> 1]);
                    psum[mt][i >> 1] += p;
                    Ps[rr * QLD + cl] = f2tf(p);
                }
        #pragma unroll
        for (int mt = 0; mt < 2; mt++)
            #pragma unroll
            for (int rh = 0; rh < 2; rh++) {
                float p = psum[mt][rh];
                p += __shfl_xor_sync(0xffffffffu, p, 1);
                p += __shfl_xor_sync(0xffffffffu, p, 2);
                psum[mt][rh] = p;
            }
        if (c == 0) {
            #pragma unroll
            for (int mt = 0; mt < 2; mt++)
                #pragma unroll
                for (int rh = 0; rh < 2; rh++)
                    rsum[wn * 128 + m0b + mt * 16 + rh * 8 + g] = psum[mt][rh];
        }
        __syncthreads();   // also: all warps done reading K tile

        if (wn == 0 && c == 0) {
            #pragma unroll
            for (int mt = 0; mt < 2; mt++)
                #pragma unroll
                for (int rh = 0; rh < 2; rh++) {
                    const int rr = m0b + mt * 16 + rh * 8 + g;
                    l_state[rr] = l_state[rr] * scal[mt][rh] + rsum[rr] + rsum[128 + rr];
                    m_state[rr] = mnew[mt][rh];
                }
        }
        #pragma unroll
        for (int mt = 0; mt < 2; mt++)
            #pragma unroll
            for (int nt = 0; nt < 8; nt++)
                #pragma unroll
                for (int i = 0; i < 4; i++)
                    acc_o[mt][nt][i] *= scal[mt][i >> 1];

        // ---- stage FULL V tile (128x128) stride VLD ----
        #pragma unroll
        for (int s = 0; s < 16; s++) {
            const int idx = s * 256 + tid;
            const int row = idx >> 5;
            const int cf  = (idx & 31) << 2;
            cp16(kvb + (row * VLD + cf) * 4, &Vg[(size_t)row * DHEAD + cf]);
        }
        cp_commit();
        cp_wait<0>();
        __syncthreads();

        // ---- O += P @ V : 16 uninterrupted kk steps ----
        #pragma unroll
        for (int kk = 0; kk < 128; kk += 8) {
            uint32_t af[2][4];
            #pragma unroll
            for (int mt = 0; mt < 2; mt++) {
                const int m0 = m0b + mt * 16 + g;
                const float2 p0 = *reinterpret_cast<const float2*>(&Ps[m0 * QLD + kk + 2 * c]);
                const float2 p1 = *reinterpret_cast<const float2*>(&Ps[(m0 + 8) * QLD + kk + 2 * c]);
                af[mt][0] = __float_as_uint(p0.x); af[mt][2] = __float_as_uint(p0.y);
                af[mt][1] = __float_as_uint(p1.x); af[mt][3] = __float_as_uint(p1.y);
            }
            #pragma unroll
            for (int nt = 0; nt < 8; nt++) {
                const int n0 = wn * 64 + nt * 8 + g;
                const uint32_t b0 = __float_as_uint(KV[(kk + 2 * c) * VLD + n0]);
                const uint32_t b1 = __float_as_uint(KV[(kk + 2 * c + 1) * VLD + n0]);
                #pragma unroll
                for (int mt = 0; mt < 2; mt++)
                    mma_tf32(acc_o[mt][nt], af[mt], b0, b1);
            }
        }
    }

    float inv[2][2];
    #pragma unroll
    for (int mt = 0; mt < 2; mt++)
        #pragma unroll
        for (int rh = 0; rh < 2; rh++)
            inv[mt][rh] = 1.0f / l_state[m0b + mt * 16 + rh * 8 + g];
    #pragma unroll
    for (int mt = 0; mt < 2; mt++)
        #pragma unroll
        for (int nt = 0; nt < 8; nt++)
            #pragma unroll
            for (int i = 0; i < 4; i++) {
                const int q  = rb + acc_row8(wm, mt, g, i);
                const int dh = acc_col8(wn, nt, c, i);
                g_attn[(size_t)q * DMODEL + h * DHEAD + dh] =
                    f2tf(acc_o[mt][nt][i] * inv[mt][i >> 1]);
            }
}

// ---------------- kernel 4: output projection -------------------------------
__global__ __launch_bounds__(256, 1) void oproj_kernel(const float* __restrict__ wo,
                                                       float* __restrict__ out) {
    extern __shared__ float dsm[];
    const int rb = blockIdx.x * 256, cb = blockIdx.y * 128;
    float acc[4][8][4] = {};
    gemm256(g_attn + (size_t)rb * DMODEL, DMODEL,
            wo + (size_t)cb * DMODEL, DMODEL, acc, dsm);

    const int tid = threadIdx.x, warp = tid >> 5, lane = tid & 31;
    const int wm = warp >> 1, wn = warp & 1, g = lane >> 2, c = lane & 3;
    #pragma unroll
    for (int mt = 0; mt < 4; mt++)
        #pragma unroll
        for (int nt = 0; nt < 8; nt++)
            #pragma unroll
            for (int i = 0; i < 4; i++) {
                const int s = rb + wm * 64 + mt * 16 + g + ((i >> 1) << 3);
                const int d = cb + wn * 64 + nt * 8 + c * 2 + (i & 1);
                out[(size_t)s * DMODEL + d] = acc[mt][nt][i];
            }
}

// ---------------- launch ----------------------------------------------------
extern "C" void kernel_launch(void* const* d_in, const int* in_sizes, int n_in,
                              void* d_out, int out_size) {
    (void)in_sizes; (void)n_in; (void)out_size;
    const float* x  = (const float*)d_in[0];
    const float* rc = (const float*)d_in[1];
    const float* rs = (const float*)d_in[2];
    const float* wq = (const float*)d_in[4];
    const float* wk = (const float*)d_in[5];
    const float* wv = (const float*)d_in[6];
    const float* wo = (const float*)d_in[7];
    float* out = (float*)d_out;

    const int dense_smem = DSM_TOT * (int)sizeof(float);   // 120 KB
    const int flash_smem = FL_TOT * (int)sizeof(float);    // ~212 KB
    cudaFuncSetAttribute(flash_kernel,
                         cudaFuncAttributeMaxDynamicSharedMemorySize, flash_smem);
    cudaFuncSetAttribute(qkv_kernel,
                         cudaFuncAttributeMaxDynamicSharedMemorySize, dense_smem);
    cudaFuncSetAttribute(oproj_kernel,
                         cudaFuncAttributeMaxDynamicSharedMemorySize, dense_smem);

    qkv_kernel<<<dim3(8, 16, 3), 256, dense_smem>>>(x, wq, wk, wv);
    rope_kernel<<<16384, 256>>>(rc, rs);
    flash_kernel<<<256, 256, flash_smem>>>();
    oproj_kernel<<<dim3(8, 16), 256, dense_smem>>>(wo, out);
}